// round 14
// baseline (speedup 1.0000x reference)
#include <cuda_runtime.h>
#include <cuda_fp16.h>
#include <math.h>
#include <stdint.h>
#include <stddef.h>

// Problem constants
#define BB   4
#define TT   2048
#define CC   2048
#define NH   16
#define HD   128
#define MROWS (BB * TT)          // 8192
#define LOG2E 1.4426950408889634f
#define QSCALE 0.12751743502016435f   // (1/sqrt(128)) * log2(e)

// ---------------------------------------------------------------------------
// Scratch (device globals)
// ---------------------------------------------------------------------------
__device__ __half g_x[BB * TT * CC];       // x single fp16
__device__ __half g_at[BB * TT * CC];      // attention out, single fp16
__device__ __half g_w[4][CC * CC];         // weights, single fp16
__device__ __half g_q[BB * NH * TT * HD];  // (b,h,t,d) Q single fp16 (pre-scaled)
__device__ __half g_k[BB * NH * TT * HD];  // K single fp16
__device__ __half g_v[BB * NH * TT * HD];  // V single fp16

// ---------------------------------------------------------------------------
// Helpers
// ---------------------------------------------------------------------------
__device__ __forceinline__ uint32_t smem_u32(const void* p) {
    uint32_t a;
    asm("{ .reg .u64 t; cvta.to.shared.u64 t, %1; cvt.u32.u64 %0, t; }"
        : "=r"(a) : "l"(p));
    return a;
}
__device__ __forceinline__ void cp16(uint32_t dst, const void* src) {
    asm volatile("cp.async.cg.shared.global [%0], [%1], 16;"
                 :: "r"(dst), "l"(src) : "memory");
}
__device__ __forceinline__ void ldsm_x4(uint32_t* r, uint32_t addr) {
    asm volatile("ldmatrix.sync.aligned.m8n8.x4.shared.b16 {%0,%1,%2,%3}, [%4];"
        : "=r"(r[0]), "=r"(r[1]), "=r"(r[2]), "=r"(r[3]) : "r"(addr));
}
__device__ __forceinline__ void ldsm_x4t(uint32_t* r, uint32_t addr) {
    asm volatile("ldmatrix.sync.aligned.m8n8.x4.trans.shared.b16 {%0,%1,%2,%3}, [%4];"
        : "=r"(r[0]), "=r"(r[1]), "=r"(r[2]), "=r"(r[3]) : "r"(addr));
}
// fp16 MMA m16n8k16, fp32 accumulate
__device__ __forceinline__ void mma16816(float* c, const uint32_t* a, const uint32_t* b) {
    asm volatile("mma.sync.aligned.m16n8k16.row.col.f32.f16.f16.f32 "
        "{%0,%1,%2,%3}, {%4,%5,%6,%7}, {%8,%9}, {%0,%1,%2,%3};"
        : "+f"(c[0]), "+f"(c[1]), "+f"(c[2]), "+f"(c[3])
        : "r"(a[0]), "r"(a[1]), "r"(a[2]), "r"(a[3]), "r"(b[0]), "r"(b[1]));
}
__device__ __forceinline__ uint32_t pack_h2(float a, float b) {
    __half2 hh; hh.x = __float2half_rn(a); hh.y = __float2half_rn(b);
    return *(uint32_t*)&hh;
}

// ---------------------------------------------------------------------------
// fp32 -> fp16 converts (ILP 2)
// ---------------------------------------------------------------------------
__global__ void conv_kernel(const float* __restrict__ in,
                            __half* __restrict__ out, int n4)
{
    int i = (blockIdx.x * blockDim.x + threadIdx.x) * 2;
    if (i + 1 >= n4) {
        if (i >= n4) return;
        float4 v = ((const float4*)in)[i];
        __align__(8) __half h[4];
        h[0] = __float2half_rn(v.x); h[1] = __float2half_rn(v.y);
        h[2] = __float2half_rn(v.z); h[3] = __float2half_rn(v.w);
        ((uint2*)out)[i] = *(uint2*)h;
        return;
    }
    float4 v0 = ((const float4*)in)[i];
    float4 v1 = ((const float4*)in)[i + 1];
    __align__(8) __half h0[4], h1[4];
    h0[0] = __float2half_rn(v0.x); h0[1] = __float2half_rn(v0.y);
    h0[2] = __float2half_rn(v0.z); h0[3] = __float2half_rn(v0.w);
    h1[0] = __float2half_rn(v1.x); h1[1] = __float2half_rn(v1.y);
    h1[2] = __float2half_rn(v1.z); h1[3] = __float2half_rn(v1.w);
    ((uint2*)out)[i]     = *(uint2*)h0;
    ((uint2*)out)[i + 1] = *(uint2*)h1;
}

// 4 weight matrices in one launch (dst contiguous), ILP 2
__global__ void conv4_kernel(const float* __restrict__ w0, const float* __restrict__ w1,
                             const float* __restrict__ w2, const float* __restrict__ w3,
                             __half* __restrict__ out)
{
    const int per = (CC * CC) / 4;           // float4s per matrix
    int i = (blockIdx.x * blockDim.x + threadIdx.x) * 2;
    if (i >= 4 * per) return;
#pragma unroll
    for (int u = 0; u < 2; u++) {
        const int idx = i + u;
        const int m = idx / per, r = idx % per;
        const float* src = (m == 0) ? w0 : (m == 1) ? w1 : (m == 2) ? w2 : w3;
        float4 v = ((const float4*)src)[r];
        __align__(8) __half h[4];
        h[0] = __float2half_rn(v.x); h[1] = __float2half_rn(v.y);
        h[2] = __float2half_rn(v.z); h[3] = __float2half_rn(v.w);
        ((uint2*)out)[idx] = *(uint2*)h;
    }
}

// ---------------------------------------------------------------------------
// Common GEMM geometry
// ---------------------------------------------------------------------------
#define BM 128
#define BN 128
#define BK 64
#define KCH (CC / BK)                 // 32
#define TILE_B 16384                  // 128 rows x 128 bytes
#define NSTG 4
#define STG_B (2 * TILE_B)            // A, W
static constexpr unsigned GEMM_SMEM = NSTG * STG_B;   // 131072

// ---------------------------------------------------------------------------
// Fused QKV GEMM (1-pass fp16):
//   grid (48, 64); bx>>4 selects {Q,K,V}; bx&15 = head/N-tile.
//   All outputs single fp16, head layout. Q pre-scaled by QSCALE.
// ---------------------------------------------------------------------------
__global__ __launch_bounds__(256, 1)
void gemm_qkv_kernel(const __half* __restrict__ X,
                     const __half* __restrict__ Wbase,
                     const float* __restrict__ bq,
                     const float* __restrict__ bk,
                     const float* __restrict__ bv,
                     __half* __restrict__ qp, __half* __restrict__ kp,
                     __half* __restrict__ vp)
{
    extern __shared__ char smem[];
    const uint32_t sb = smem_u32(smem);
    const int tid  = threadIdx.x;
    const int lane = tid & 31;
    const int wid  = tid >> 5;
    const int wr   = wid >> 2;
    const int wc   = wid & 3;
    const int bx = blockIdx.x, by = blockIdx.y;
    const int sel = bx >> 4;              // 0=Q, 1=K, 2=V
    const int hx  = bx & 15;              // head / N-tile

    const float* bias = (sel == 0) ? bq : (sel == 1) ? bk : bv;
    const float escale = (sel == 0) ? QSCALE : 1.0f;
    __half* outp = (sel == 0) ? qp : (sel == 1) ? kp : vp;

    const __half* srcs[2] = {
        X + (size_t)by * BM * CC,
        Wbase + (size_t)sel * CC * CC + (size_t)hx * BN * CC
    };

    auto load_stage = [&](int stg, int kc) {
        const uint32_t base = sb + stg * STG_B;
#pragma unroll
        for (int ti = 0; ti < 2; ti++) {
            const __half* src = srcs[ti];
            const uint32_t tb = base + ti * TILE_B;
#pragma unroll
            for (int i = 0; i < 4; i++) {
                const int idx = tid + i * 256;
                const int row = idx >> 3;
                const int ch  = idx & 7;
                const uint32_t dst = tb + row * 128 + ((ch ^ (row & 7)) << 4);
                cp16(dst, src + (size_t)row * CC + kc + ch * 8);
            }
        }
        asm volatile("cp.async.commit_group;" ::: "memory");
    };

    const int a_lr = lane & 15;
    const int a_hk = lane >> 4;
    uint32_t a_off[4]; int a_sel[4];
#pragma unroll
    for (int mt = 0; mt < 4; mt++) {
        const int r = wr * 64 + mt * 16 + a_lr;
        a_off[mt] = r * 128;
        a_sel[mt] = r & 7;
    }
    const int b_rloc = ((lane >> 4) << 3) + (lane & 7);
    const int b_ch   = (lane >> 3) & 1;
    uint32_t b_off[2]; int b_sel2[2];
#pragma unroll
    for (int ntp = 0; ntp < 2; ntp++) {
        const int r = wc * 32 + ntp * 16 + b_rloc;
        b_off[ntp] = r * 128;
        b_sel2[ntp] = r & 7;
    }

    float c[4][4][4];
#pragma unroll
    for (int mt = 0; mt < 4; mt++)
#pragma unroll
        for (int nt = 0; nt < 4; nt++)
#pragma unroll
            for (int i = 0; i < 4; i++) c[mt][nt][i] = 0.f;

    load_stage(0, 0);
    load_stage(1, BK);
    load_stage(2, 2 * BK);

    for (int chk = 0; chk < KCH; chk++) {
        const int rem = KCH - 1 - chk;
        if (rem >= 2)      asm volatile("cp.async.wait_group 2;" ::: "memory");
        else if (rem == 1) asm volatile("cp.async.wait_group 1;" ::: "memory");
        else               asm volatile("cp.async.wait_group 0;" ::: "memory");
        __syncthreads();

        const uint32_t base = sb + (chk % NSTG) * STG_B;
#pragma unroll
        for (int ks = 0; ks < 4; ks++) {
            uint32_t ah[4][4], bf[2][4];
            const int ca = ks * 2 + a_hk;
            const int cb = ks * 2 + b_ch;
#pragma unroll
            for (int mt = 0; mt < 4; mt++)
                ldsm_x4(ah[mt], base + a_off[mt] + (uint32_t)(((ca ^ a_sel[mt])) << 4));
#pragma unroll
            for (int ntp = 0; ntp < 2; ntp++)
                ldsm_x4(bf[ntp], base + TILE_B + b_off[ntp] + (uint32_t)(((cb ^ b_sel2[ntp])) << 4));
#pragma unroll
            for (int mt = 0; mt < 4; mt++)
#pragma unroll
                for (int nt = 0; nt < 4; nt++)
                    mma16816(c[mt][nt], ah[mt], &bf[nt >> 1][(nt & 1) * 2]);
        }

        if (chk + 3 < KCH) load_stage((chk + 3) % NSTG, (chk + 3) * BK);
    }

    // ---- epilogue (head layout, single fp16) ----
    const int t4 = lane >> 2;
    const int t2 = (lane & 3) * 2;
#pragma unroll
    for (int mt = 0; mt < 4; mt++) {
        const int r0 = by * BM + wr * 64 + mt * 16 + t4;
        const int r1 = r0 + 8;
#pragma unroll
        for (int nt = 0; nt < 4; nt++) {
            const int col = hx * BN + wc * 32 + nt * 8 + t2;
            const float bi0 = bias[col], bi1 = bias[col + 1];
            const float v00 = (c[mt][nt][0] + bi0) * escale;
            const float v01 = (c[mt][nt][1] + bi1) * escale;
            const float v10 = (c[mt][nt][2] + bi0) * escale;
            const float v11 = (c[mt][nt][3] + bi1) * escale;
            const int d = col & 127;
            const int b0 = r0 >> 11, t0 = r0 & 2047;
            const int b1 = r1 >> 11, t1 = r1 & 2047;
            const size_t i0 = (((size_t)(b0 * NH + hx)) * TT + t0) * HD + d;
            const size_t i1 = (((size_t)(b1 * NH + hx)) * TT + t1) * HD + d;
            *(uint32_t*)&outp[i0] = pack_h2(v00, v01);
            *(uint32_t*)&outp[i1] = pack_h2(v10, v11);
        }
    }
}

// ---------------------------------------------------------------------------
// 1-pass fp16 GEMM (output projection): out = att @ Wp^T + bp, fp32 out.
// grid (16, 64).
// ---------------------------------------------------------------------------
__global__ __launch_bounds__(256, 1)
void gemm1_tc_kernel(const __half* __restrict__ A,
                     const __half* __restrict__ W,
                     const float* __restrict__ bias,
                     float* __restrict__ out)
{
    extern __shared__ char smem[];
    const uint32_t sb = smem_u32(smem);
    const int tid  = threadIdx.x;
    const int lane = tid & 31;
    const int wid  = tid >> 5;
    const int wr   = wid >> 2;
    const int wc   = wid & 3;
    const int bx = blockIdx.x, by = blockIdx.y;

    const __half* srcs[2] = {
        A + (size_t)by * BM * CC,
        W + (size_t)bx * BN * CC
    };

    auto load_stage = [&](int stg, int kc) {
        const uint32_t base = sb + stg * STG_B;
#pragma unroll
        for (int ti = 0; ti < 2; ti++) {
            const __half* src = srcs[ti];
            const uint32_t tb = base + ti * TILE_B;
#pragma unroll
            for (int i = 0; i < 4; i++) {
                const int idx = tid + i * 256;
                const int row = idx >> 3;
                const int ch  = idx & 7;
                const uint32_t dst = tb + row * 128 + ((ch ^ (row & 7)) << 4);
                cp16(dst, src + (size_t)row * CC + kc + ch * 8);
            }
        }
        asm volatile("cp.async.commit_group;" ::: "memory");
    };

    const int a_lr = lane & 15;
    const int a_hk = lane >> 4;
    uint32_t a_off[4]; int a_sel[4];
#pragma unroll
    for (int mt = 0; mt < 4; mt++) {
        const int r = wr * 64 + mt * 16 + a_lr;
        a_off[mt] = r * 128;
        a_sel[mt] = r & 7;
    }
    const int b_rloc = ((lane >> 4) << 3) + (lane & 7);
    const int b_ch   = (lane >> 3) & 1;
    uint32_t b_off[2]; int b_sel2[2];
#pragma unroll
    for (int ntp = 0; ntp < 2; ntp++) {
        const int r = wc * 32 + ntp * 16 + b_rloc;
        b_off[ntp] = r * 128;
        b_sel2[ntp] = r & 7;
    }

    float c[4][4][4];
#pragma unroll
    for (int mt = 0; mt < 4; mt++)
#pragma unroll
        for (int nt = 0; nt < 4; nt++)
#pragma unroll
            for (int i = 0; i < 4; i++) c[mt][nt][i] = 0.f;

    load_stage(0, 0);
    load_stage(1, BK);
    load_stage(2, 2 * BK);

    for (int chk = 0; chk < KCH; chk++) {
        const int rem = KCH - 1 - chk;
        if (rem >= 2)      asm volatile("cp.async.wait_group 2;" ::: "memory");
        else if (rem == 1) asm volatile("cp.async.wait_group 1;" ::: "memory");
        else               asm volatile("cp.async.wait_group 0;" ::: "memory");
        __syncthreads();

        const uint32_t base = sb + (chk % NSTG) * STG_B;
#pragma unroll
        for (int ks = 0; ks < 4; ks++) {
            uint32_t ah[4][4], bf[2][4];
            const int ca = ks * 2 + a_hk;
            const int cb = ks * 2 + b_ch;
#pragma unroll
            for (int mt = 0; mt < 4; mt++)
                ldsm_x4(ah[mt], base + a_off[mt] + (uint32_t)(((ca ^ a_sel[mt])) << 4));
#pragma unroll
            for (int ntp = 0; ntp < 2; ntp++)
                ldsm_x4(bf[ntp], base + TILE_B + b_off[ntp] + (uint32_t)(((cb ^ b_sel2[ntp])) << 4));
#pragma unroll
            for (int mt = 0; mt < 4; mt++)
#pragma unroll
                for (int nt = 0; nt < 4; nt++)
                    mma16816(c[mt][nt], ah[mt], &bf[nt >> 1][(nt & 1) * 2]);
        }

        if (chk + 3 < KCH) load_stage((chk + 3) % NSTG, (chk + 3) * BK);
    }

    const int t4 = lane >> 2;
    const int t2 = (lane & 3) * 2;
#pragma unroll
    for (int mt = 0; mt < 4; mt++) {
        const int r0 = by * BM + wr * 64 + mt * 16 + t4;
        const int r1 = r0 + 8;
#pragma unroll
        for (int nt = 0; nt < 4; nt++) {
            const int col = bx * BN + wc * 32 + nt * 8 + t2;
            const float bi0 = bias[col], bi1 = bias[col + 1];
            float2 v0 = {c[mt][nt][0] + bi0, c[mt][nt][1] + bi1};
            float2 v1 = {c[mt][nt][2] + bi0, c[mt][nt][3] + bi1};
            *(float2*)(out + (size_t)r0 * CC + col) = v0;
            *(float2*)(out + (size_t)r1 * CC + col) = v1;
        }
    }
}

// ---------------------------------------------------------------------------
// Tensor-core flash attention, fp16 1-pass, exp2 domain.
// Grid: (T/128, B*H). 256 threads = 8 warps x 16 query rows.
// Q single (pre-scaled), K single, P single, V single.
// KV tiles of 64, double-buffered cp.async. Output: single fp16 (b,t,c).
// Smem: Q[0:32K], stage s at 32K + 32K*s: {K:0, V:16K}. Total 96KB.
// ---------------------------------------------------------------------------
static constexpr unsigned ATT_SMEM = 98304;

__global__ __launch_bounds__(256, 1)
void attn_tc_kernel(const __half* __restrict__ qp,
                    const __half* __restrict__ kp, const __half* __restrict__ vp,
                    const float* __restrict__ mask,
                    __half* __restrict__ outp)
{
    extern __shared__ char smem[];
    const uint32_t sb = smem_u32(smem);
    const int tid = threadIdx.x, lane = tid & 31, warp = tid >> 5;
    const int qb = gridDim.x - 1 - blockIdx.x;     // long CTAs first
    const int bh = blockIdx.y;
    const int b = bh >> 4, h = bh & 15;
    const int q0 = qb * 128;
    const int jmax = 2 * qb + 2;
    const size_t bhoff = (size_t)bh * TT * HD;

    // ---- Q tile load ----
    {
        const __half* s0 = qp + bhoff + (size_t)q0 * HD;
#pragma unroll
        for (int i = 0; i < 8; i++) {
            const int idx = tid + i * 256;          // 2048 chunks
            const int r = idx >> 4, ch = idx & 15;
            const uint32_t off = r * 256 + ((ch ^ (r & 7)) << 4);
            cp16(sb + off, s0 + (size_t)r * HD + ch * 8);
        }
        asm volatile("cp.async.commit_group;" ::: "memory");
    }

    auto loadKV = [&](int j, int st) {
        const uint32_t base = sb + 32768 + st * 32768;
        const int kv0 = j * 64;
        const __half* srcs[2] = {
            kp + bhoff + (size_t)kv0 * HD, vp + bhoff + (size_t)kv0 * HD };
#pragma unroll
        for (int i = 0; i < 8; i++) {
            const int idx = tid + i * 256;
            const int mat = idx >> 10, r = (idx >> 4) & 63, ch = idx & 15;
            cp16(base + mat * 16384 + r * 256 + ((ch ^ (r & 7)) << 4),
                 srcs[mat] + (size_t)r * HD + ch * 8);
        }
        asm volatile("cp.async.commit_group;" ::: "memory");
    };

    loadKV(0, 0);
    loadKV(1, 1);

    float o[16][4];
#pragma unroll
    for (int n = 0; n < 16; n++)
#pragma unroll
        for (int i = 0; i < 4; i++) o[n][i] = 0.f;
    float m0 = -1e30f, m1 = -1e30f, l0 = 0.f, l1 = 0.f;

    const int qrow  = warp * 16 + (lane & 15);
    const uint32_t a_base = qrow * 256;
    const int a_sel = qrow & 7;
    const int a_kh  = lane >> 4;
    const int kb_rloc = ((lane >> 4) << 3) + (lane & 7);
    const int kb_ch   = (lane >> 3) & 1;
    const int v_rloc  = lane & 15;
    const int v_chh   = lane >> 4;

    const int qg0 = q0 + warp * 16 + (lane >> 2);
    const int qg1 = qg0 + 8;

    for (int j = 0; j < jmax; j++) {
        const int kv0 = j * 64;
        const int st = j & 1;
        if (j + 1 < jmax) asm volatile("cp.async.wait_group 1;" ::: "memory");
        else              asm volatile("cp.async.wait_group 0;" ::: "memory");
        __syncthreads();

        const uint32_t KB = sb + 32768 + st * 32768;
        const uint32_t VB = KB + 16384;

        // ---- S = Q K^T (1 pass), 16x64 per warp ----
        float s[8][4];
#pragma unroll
        for (int n = 0; n < 8; n++)
#pragma unroll
            for (int i = 0; i < 4; i++) s[n][i] = 0.f;

#pragma unroll
        for (int ks = 0; ks < 8; ks++) {
            uint32_t qf[4];
            const uint32_t ca = (uint32_t)(((2 * ks + a_kh) ^ a_sel) << 4);
            ldsm_x4(qf, sb + a_base + ca);
            uint32_t kf[16];
#pragma unroll
            for (int i = 0; i < 4; i++) {
                const int r = 16 * i + kb_rloc;
                const uint32_t off = r * 256 + (((2 * ks + kb_ch) ^ (r & 7)) << 4);
                ldsm_x4(&kf[4 * i], KB + off);
            }
#pragma unroll
            for (int n = 0; n < 8; n++)
                mma16816(s[n], qf, &kf[2 * n]);
        }

        // ---- mask + causal ----
        const bool need_mask = (j >= 2 * qb);
#pragma unroll
        for (int n = 0; n < 8; n++) {
            const int kg = kv0 + 8 * n + 2 * (lane & 3);
            const float2 mv = *(const float2*)&mask[b * TT + kg];
            const float am0 = mv.x * LOG2E, am1 = mv.y * LOG2E;
            s[n][0] += am0; s[n][1] += am1;
            s[n][2] += am0; s[n][3] += am1;
            if (need_mask) {
                if (kg     > qg0) s[n][0] = -1e30f;
                if (kg + 1 > qg0) s[n][1] = -1e30f;
                if (kg     > qg1) s[n][2] = -1e30f;
                if (kg + 1 > qg1) s[n][3] = -1e30f;
            }
        }

        // ---- online softmax (quad-local) ----
        float mx0 = m0, mx1 = m1;
#pragma unroll
        for (int n = 0; n < 8; n++) {
            mx0 = fmaxf(mx0, fmaxf(s[n][0], s[n][1]));
            mx1 = fmaxf(mx1, fmaxf(s[n][2], s[n][3]));
        }
        mx0 = fmaxf(mx0, __shfl_xor_sync(0xffffffffu, mx0, 1));
        mx0 = fmaxf(mx0, __shfl_xor_sync(0xffffffffu, mx0, 2));
        mx1 = fmaxf(mx1, __shfl_xor_sync(0xffffffffu, mx1, 1));
        mx1 = fmaxf(mx1, __shfl_xor_sync(0xffffffffu, mx1, 2));
        const float al0 = exp2f(m0 - mx0);
        const float al1 = exp2f(m1 - mx1);
        m0 = mx0; m1 = mx1;
        float sum0 = 0.f, sum1 = 0.f;
#pragma unroll
        for (int n = 0; n < 8; n++) {
            s[n][0] = exp2f(s[n][0] - m0);
            s[n][1] = exp2f(s[n][1] - m0);
            s[n][2] = exp2f(s[n][2] - m1);
            s[n][3] = exp2f(s[n][3] - m1);
            sum0 += s[n][0] + s[n][1];
            sum1 += s[n][2] + s[n][3];
        }
        sum0 += __shfl_xor_sync(0xffffffffu, sum0, 1);
        sum0 += __shfl_xor_sync(0xffffffffu, sum0, 2);
        sum1 += __shfl_xor_sync(0xffffffffu, sum1, 1);
        sum1 += __shfl_xor_sync(0xffffffffu, sum1, 2);
        l0 = l0 * al0 + sum0;
        l1 = l1 * al1 + sum1;
#pragma unroll
        for (int n = 0; n < 16; n++) {
            o[n][0] *= al0; o[n][1] *= al0;
            o[n][2] *= al1; o[n][3] *= al1;
        }

        // ---- O += P V (register repack, 1 pass) ----
#pragma unroll
        for (int kv = 0; kv < 4; kv++) {
            uint32_t pa[4];
            pa[0] = pack_h2(s[2 * kv][0],     s[2 * kv][1]);
            pa[1] = pack_h2(s[2 * kv][2],     s[2 * kv][3]);
            pa[2] = pack_h2(s[2 * kv + 1][0], s[2 * kv + 1][1]);
            pa[3] = pack_h2(s[2 * kv + 1][2], s[2 * kv + 1][3]);
            const int vr = 16 * kv + v_rloc;
            const uint32_t vro = vr * 256;
            const int vsel = vr & 7;
#pragma unroll
            for (int i = 0; i < 8; i++) {
                const uint32_t ch = (uint32_t)(((2 * i + v_chh) ^ vsel) << 4);
                uint32_t vf[4];
                ldsm_x4t(vf, VB + vro + ch);
                mma16816(o[2 * i],     pa, &vf[0]);
                mma16816(o[2 * i + 1], pa, &vf[2]);
            }
        }

        __syncthreads();
        if (j + 2 < jmax) loadKV(j + 2, st);
    }

    // ---- epilogue: normalize, single fp16, write (b,t,c) ----
    const float inv0 = 1.f / l0, inv1 = 1.f / l1;
    const size_t r0base = ((size_t)b * TT + qg0) * CC + h * HD;
    const size_t r1base = ((size_t)b * TT + qg1) * CC + h * HD;
#pragma unroll
    for (int n = 0; n < 16; n++) {
        const int d = 8 * n + 2 * (lane & 3);
        *(uint32_t*)&outp[r0base + d] = pack_h2(o[n][0] * inv0, o[n][1] * inv0);
        *(uint32_t*)&outp[r1base + d] = pack_h2(o[n][2] * inv1, o[n][3] * inv1);
    }
}

// ---------------------------------------------------------------------------
// Launcher
// ---------------------------------------------------------------------------
extern "C" void kernel_launch(void* const* d_in, const int* in_sizes, int n_in,
                              void* d_out, int out_size)
{
    const float* x    = (const float*)d_in[0];
    const float* mask = (const float*)d_in[1];
    const float* bq   = (const float*)d_in[3];
    const float* bk   = (const float*)d_in[5];
    const float* bv   = (const float*)d_in[7];
    const float* bp   = (const float*)d_in[9];
    float* out = (float*)d_out;

    __half *xp, *at, *w, *qp, *kp, *vp;
    cudaGetSymbolAddress((void**)&xp, g_x);
    cudaGetSymbolAddress((void**)&at, g_at);
    cudaGetSymbolAddress((void**)&w,  g_w);
    cudaGetSymbolAddress((void**)&qp, g_q);
    cudaGetSymbolAddress((void**)&kp, g_k);
    cudaGetSymbolAddress((void**)&vp, g_v);

    cudaFuncSetAttribute(gemm_qkv_kernel,
                         cudaFuncAttributeMaxDynamicSharedMemorySize, GEMM_SMEM);
    cudaFuncSetAttribute(gemm1_tc_kernel,
                         cudaFuncAttributeMaxDynamicSharedMemorySize, GEMM_SMEM);
    cudaFuncSetAttribute(attn_tc_kernel,
                         cudaFuncAttributeMaxDynamicSharedMemorySize, ATT_SMEM);

    // 1. convert x and weights to fp16
    {
        const int n4x = (BB * TT * CC) / 4;
        conv_kernel<<<(n4x / 2 + 255) / 256, 256>>>(x, xp, n4x);
        const int n4w = CC * CC;          // total float4s over 4 matrices
        conv4_kernel<<<(n4w / 2 + 255) / 256, 256>>>(
            (const float*)d_in[2], (const float*)d_in[4],
            (const float*)d_in[6], (const float*)d_in[8], w);
    }

    // 2. fused QKV projection (1-pass; Q pre-scaled; all single fp16)
    gemm_qkv_kernel<<<dim3(48, MROWS / BM), 256, GEMM_SMEM>>>(
        xp, w, bq, bk, bv, qp, kp, vp);

    // 3. flash attention -> single fp16 (b,t,c)
    attn_tc_kernel<<<dim3(TT / 128, BB * NH), 256, ATT_SMEM>>>(
        qp, kp, vp, mask, at);

    // 4. output projection (1-pass) -> fp32 out
    gemm1_tc_kernel<<<dim3(CC / BN, MROWS / BM), 256, GEMM_SMEM>>>(
        at, w + 3 * (size_t)CC * CC, bp, out);
}

// round 15
// speedup vs baseline: 1.4431x; 1.4431x over previous
#include <cuda_runtime.h>
#include <cuda_fp16.h>
#include <math.h>
#include <stdint.h>
#include <stddef.h>

// Problem constants
#define BB   4
#define TT   2048
#define CC   2048
#define NH   16
#define HD   128
#define MROWS (BB * TT)          // 8192
#define LOG2E 1.4426950408889634f
#define QSCALE 0.12751743502016435f   // (1/sqrt(128)) * log2(e)

// ---------------------------------------------------------------------------
// Scratch (device globals)
// ---------------------------------------------------------------------------
__device__ __half g_x[BB * TT * CC];       // x single fp16
__device__ __half g_at[BB * TT * CC];      // attention out, single fp16
__device__ __half g_w[4][CC * CC];         // weights, single fp16
__device__ __half g_qh[BB * NH * TT * HD]; // (b,h,t,d) Q split hi
__device__ __half g_ql[BB * NH * TT * HD]; // Q split lo
__device__ __half g_kh[BB * NH * TT * HD]; // K single fp16
__device__ __half g_vh[BB * NH * TT * HD]; // V single fp16

// ---------------------------------------------------------------------------
// Helpers
// ---------------------------------------------------------------------------
__device__ __forceinline__ uint32_t smem_u32(const void* p) {
    uint32_t a;
    asm("{ .reg .u64 t; cvta.to.shared.u64 t, %1; cvt.u32.u64 %0, t; }"
        : "=r"(a) : "l"(p));
    return a;
}
__device__ __forceinline__ void cp16(uint32_t dst, const void* src) {
    asm volatile("cp.async.cg.shared.global [%0], [%1], 16;"
                 :: "r"(dst), "l"(src) : "memory");
}
__device__ __forceinline__ void ldsm_x4(uint32_t* r, uint32_t addr) {
    asm volatile("ldmatrix.sync.aligned.m8n8.x4.shared.b16 {%0,%1,%2,%3}, [%4];"
        : "=r"(r[0]), "=r"(r[1]), "=r"(r[2]), "=r"(r[3]) : "r"(addr));
}
__device__ __forceinline__ void ldsm_x4t(uint32_t* r, uint32_t addr) {
    asm volatile("ldmatrix.sync.aligned.m8n8.x4.trans.shared.b16 {%0,%1,%2,%3}, [%4];"
        : "=r"(r[0]), "=r"(r[1]), "=r"(r[2]), "=r"(r[3]) : "r"(addr));
}
// fp16 MMA m16n8k16, fp32 accumulate
__device__ __forceinline__ void mma16816(float* c, const uint32_t* a, const uint32_t* b) {
    asm volatile("mma.sync.aligned.m16n8k16.row.col.f32.f16.f16.f32 "
        "{%0,%1,%2,%3}, {%4,%5,%6,%7}, {%8,%9}, {%0,%1,%2,%3};"
        : "+f"(c[0]), "+f"(c[1]), "+f"(c[2]), "+f"(c[3])
        : "r"(a[0]), "r"(a[1]), "r"(a[2]), "r"(a[3]), "r"(b[0]), "r"(b[1]));
}
// pack (a,b) -> fp16x2 hi word + lo word (a in low half)
__device__ __forceinline__ void split_pack(float a, float b, uint32_t& h, uint32_t& l) {
    __half ah = __float2half_rn(a);
    __half bh = __float2half_rn(b);
    __half2 hh; hh.x = ah; hh.y = bh;
    h = *(uint32_t*)&hh;
    __half2 ll;
    ll.x = __float2half_rn(a - __half2float(ah));
    ll.y = __float2half_rn(b - __half2float(bh));
    l = *(uint32_t*)&ll;
}
__device__ __forceinline__ uint32_t pack_h2(float a, float b) {
    __half2 hh; hh.x = __float2half_rn(a); hh.y = __float2half_rn(b);
    return *(uint32_t*)&hh;
}

// ---------------------------------------------------------------------------
// fp32 -> fp16 converts (ILP 2)
// ---------------------------------------------------------------------------
__global__ void conv_kernel(const float* __restrict__ in,
                            __half* __restrict__ out, int n4)
{
    int i = (blockIdx.x * blockDim.x + threadIdx.x) * 2;
    if (i + 1 >= n4) {
        if (i >= n4) return;
        float4 v = ((const float4*)in)[i];
        __align__(8) __half h[4];
        h[0] = __float2half_rn(v.x); h[1] = __float2half_rn(v.y);
        h[2] = __float2half_rn(v.z); h[3] = __float2half_rn(v.w);
        ((uint2*)out)[i] = *(uint2*)h;
        return;
    }
    float4 v0 = ((const float4*)in)[i];
    float4 v1 = ((const float4*)in)[i + 1];
    __align__(8) __half h0[4], h1[4];
    h0[0] = __float2half_rn(v0.x); h0[1] = __float2half_rn(v0.y);
    h0[2] = __float2half_rn(v0.z); h0[3] = __float2half_rn(v0.w);
    h1[0] = __float2half_rn(v1.x); h1[1] = __float2half_rn(v1.y);
    h1[2] = __float2half_rn(v1.z); h1[3] = __float2half_rn(v1.w);
    ((uint2*)out)[i]     = *(uint2*)h0;
    ((uint2*)out)[i + 1] = *(uint2*)h1;
}

// 4 weight matrices in one launch (dst contiguous), ILP 2
__global__ void conv4_kernel(const float* __restrict__ w0, const float* __restrict__ w1,
                             const float* __restrict__ w2, const float* __restrict__ w3,
                             __half* __restrict__ out)
{
    const int per = (CC * CC) / 4;           // float4s per matrix
    int i = (blockIdx.x * blockDim.x + threadIdx.x) * 2;
    if (i >= 4 * per) return;
#pragma unroll
    for (int u = 0; u < 2; u++) {
        const int idx = i + u;
        const int m = idx / per, r = idx % per;
        const float* src = (m == 0) ? w0 : (m == 1) ? w1 : (m == 2) ? w2 : w3;
        float4 v = ((const float4*)src)[r];
        __align__(8) __half h[4];
        h[0] = __float2half_rn(v.x); h[1] = __float2half_rn(v.y);
        h[2] = __float2half_rn(v.z); h[3] = __float2half_rn(v.w);
        ((uint2*)out)[idx] = *(uint2*)h;
    }
}

// ---------------------------------------------------------------------------
// Common GEMM geometry
// ---------------------------------------------------------------------------
#define BM 128
#define BN 128
#define BK 64
#define KCH (CC / BK)                 // 32
#define TILE_B 16384                  // 128 rows x 128 bytes
#define NSTG 4
#define STG_B (2 * TILE_B)            // A, W
static constexpr unsigned GEMM_SMEM = NSTG * STG_B;   // 131072

// ---------------------------------------------------------------------------
// Fused QKV GEMM (1-pass fp16):
//   grid (48, 64); bx>>4 selects {Q,K,V}; bx&15 = head/N-tile.
//   Q -> split hi/lo (pre-scaled QSCALE); K,V -> single fp16, head layout.
// ---------------------------------------------------------------------------
__global__ __launch_bounds__(256, 1)
void gemm_qkv_kernel(const __half* __restrict__ X,
                     const __half* __restrict__ Wbase,
                     const float* __restrict__ bq,
                     const float* __restrict__ bk,
                     const float* __restrict__ bv,
                     __half* __restrict__ qh, __half* __restrict__ ql,
                     __half* __restrict__ kh, __half* __restrict__ vh)
{
    extern __shared__ char smem[];
    const uint32_t sb = smem_u32(smem);
    const int tid  = threadIdx.x;
    const int lane = tid & 31;
    const int wid  = tid >> 5;
    const int wr   = wid >> 2;
    const int wc   = wid & 3;
    const int bx = blockIdx.x, by = blockIdx.y;
    const int sel = bx >> 4;              // 0=Q, 1=K, 2=V
    const int hx  = bx & 15;              // head / N-tile

    const float* bias = (sel == 0) ? bq : (sel == 1) ? bk : bv;
    const float escale = (sel == 0) ? QSCALE : 1.0f;

    const __half* srcs[2] = {
        X + (size_t)by * BM * CC,
        Wbase + (size_t)sel * CC * CC + (size_t)hx * BN * CC
    };

    auto load_stage = [&](int stg, int kc) {
        const uint32_t base = sb + stg * STG_B;
#pragma unroll
        for (int ti = 0; ti < 2; ti++) {
            const __half* src = srcs[ti];
            const uint32_t tb = base + ti * TILE_B;
#pragma unroll
            for (int i = 0; i < 4; i++) {
                const int idx = tid + i * 256;
                const int row = idx >> 3;
                const int ch  = idx & 7;
                const uint32_t dst = tb + row * 128 + ((ch ^ (row & 7)) << 4);
                cp16(dst, src + (size_t)row * CC + kc + ch * 8);
            }
        }
        asm volatile("cp.async.commit_group;" ::: "memory");
    };

    const int a_lr = lane & 15;
    const int a_hk = lane >> 4;
    uint32_t a_off[4]; int a_sel[4];
#pragma unroll
    for (int mt = 0; mt < 4; mt++) {
        const int r = wr * 64 + mt * 16 + a_lr;
        a_off[mt] = r * 128;
        a_sel[mt] = r & 7;
    }
    const int b_rloc = ((lane >> 4) << 3) + (lane & 7);
    const int b_ch   = (lane >> 3) & 1;
    uint32_t b_off[2]; int b_sel2[2];
#pragma unroll
    for (int ntp = 0; ntp < 2; ntp++) {
        const int r = wc * 32 + ntp * 16 + b_rloc;
        b_off[ntp] = r * 128;
        b_sel2[ntp] = r & 7;
    }

    float c[4][4][4];
#pragma unroll
    for (int mt = 0; mt < 4; mt++)
#pragma unroll
        for (int nt = 0; nt < 4; nt++)
#pragma unroll
            for (int i = 0; i < 4; i++) c[mt][nt][i] = 0.f;

    load_stage(0, 0);
    load_stage(1, BK);
    load_stage(2, 2 * BK);

    for (int chk = 0; chk < KCH; chk++) {
        const int rem = KCH - 1 - chk;
        if (rem >= 2)      asm volatile("cp.async.wait_group 2;" ::: "memory");
        else if (rem == 1) asm volatile("cp.async.wait_group 1;" ::: "memory");
        else               asm volatile("cp.async.wait_group 0;" ::: "memory");
        __syncthreads();

        const uint32_t base = sb + (chk % NSTG) * STG_B;
#pragma unroll
        for (int ks = 0; ks < 4; ks++) {
            uint32_t ah[4][4], bf[2][4];
            const int ca = ks * 2 + a_hk;
            const int cb = ks * 2 + b_ch;
#pragma unroll
            for (int mt = 0; mt < 4; mt++)
                ldsm_x4(ah[mt], base + a_off[mt] + (uint32_t)(((ca ^ a_sel[mt])) << 4));
#pragma unroll
            for (int ntp = 0; ntp < 2; ntp++)
                ldsm_x4(bf[ntp], base + TILE_B + b_off[ntp] + (uint32_t)(((cb ^ b_sel2[ntp])) << 4));
#pragma unroll
            for (int mt = 0; mt < 4; mt++)
#pragma unroll
                for (int nt = 0; nt < 4; nt++)
                    mma16816(c[mt][nt], ah[mt], &bf[nt >> 1][(nt & 1) * 2]);
        }

        if (chk + 3 < KCH) load_stage((chk + 3) % NSTG, (chk + 3) * BK);
    }

    // ---- epilogue (head layout) ----
    const int t4 = lane >> 2;
    const int t2 = (lane & 3) * 2;
#pragma unroll
    for (int mt = 0; mt < 4; mt++) {
        const int r0 = by * BM + wr * 64 + mt * 16 + t4;
        const int r1 = r0 + 8;
#pragma unroll
        for (int nt = 0; nt < 4; nt++) {
            const int col = hx * BN + wc * 32 + nt * 8 + t2;
            const float bi0 = bias[col], bi1 = bias[col + 1];
            const float v00 = (c[mt][nt][0] + bi0) * escale;
            const float v01 = (c[mt][nt][1] + bi1) * escale;
            const float v10 = (c[mt][nt][2] + bi0) * escale;
            const float v11 = (c[mt][nt][3] + bi1) * escale;
            const int d = col & 127;
            const int b0 = r0 >> 11, t0 = r0 & 2047;
            const int b1 = r1 >> 11, t1 = r1 & 2047;
            const size_t i0 = (((size_t)(b0 * NH + hx)) * TT + t0) * HD + d;
            const size_t i1 = (((size_t)(b1 * NH + hx)) * TT + t1) * HD + d;
            if (sel == 0) {
                uint32_t ph, pl;
                split_pack(v00, v01, ph, pl);
                *(uint32_t*)&qh[i0] = ph; *(uint32_t*)&ql[i0] = pl;
                split_pack(v10, v11, ph, pl);
                *(uint32_t*)&qh[i1] = ph; *(uint32_t*)&ql[i1] = pl;
            } else {
                __half* o = (sel == 1) ? kh : vh;
                *(uint32_t*)&o[i0] = pack_h2(v00, v01);
                *(uint32_t*)&o[i1] = pack_h2(v10, v11);
            }
        }
    }
}

// ---------------------------------------------------------------------------
// 1-pass fp16 GEMM (output projection): out = att @ Wp^T + bp, fp32 out.
// grid (16, 64).
// ---------------------------------------------------------------------------
__global__ __launch_bounds__(256, 1)
void gemm1_tc_kernel(const __half* __restrict__ A,
                     const __half* __restrict__ W,
                     const float* __restrict__ bias,
                     float* __restrict__ out)
{
    extern __shared__ char smem[];
    const uint32_t sb = smem_u32(smem);
    const int tid  = threadIdx.x;
    const int lane = tid & 31;
    const int wid  = tid >> 5;
    const int wr   = wid >> 2;
    const int wc   = wid & 3;
    const int bx = blockIdx.x, by = blockIdx.y;

    const __half* srcs[2] = {
        A + (size_t)by * BM * CC,
        W + (size_t)bx * BN * CC
    };

    auto load_stage = [&](int stg, int kc) {
        const uint32_t base = sb + stg * STG_B;
#pragma unroll
        for (int ti = 0; ti < 2; ti++) {
            const __half* src = srcs[ti];
            const uint32_t tb = base + ti * TILE_B;
#pragma unroll
            for (int i = 0; i < 4; i++) {
                const int idx = tid + i * 256;
                const int row = idx >> 3;
                const int ch  = idx & 7;
                const uint32_t dst = tb + row * 128 + ((ch ^ (row & 7)) << 4);
                cp16(dst, src + (size_t)row * CC + kc + ch * 8);
            }
        }
        asm volatile("cp.async.commit_group;" ::: "memory");
    };

    const int a_lr = lane & 15;
    const int a_hk = lane >> 4;
    uint32_t a_off[4]; int a_sel[4];
#pragma unroll
    for (int mt = 0; mt < 4; mt++) {
        const int r = wr * 64 + mt * 16 + a_lr;
        a_off[mt] = r * 128;
        a_sel[mt] = r & 7;
    }
    const int b_rloc = ((lane >> 4) << 3) + (lane & 7);
    const int b_ch   = (lane >> 3) & 1;
    uint32_t b_off[2]; int b_sel2[2];
#pragma unroll
    for (int ntp = 0; ntp < 2; ntp++) {
        const int r = wc * 32 + ntp * 16 + b_rloc;
        b_off[ntp] = r * 128;
        b_sel2[ntp] = r & 7;
    }

    float c[4][4][4];
#pragma unroll
    for (int mt = 0; mt < 4; mt++)
#pragma unroll
        for (int nt = 0; nt < 4; nt++)
#pragma unroll
            for (int i = 0; i < 4; i++) c[mt][nt][i] = 0.f;

    load_stage(0, 0);
    load_stage(1, BK);
    load_stage(2, 2 * BK);

    for (int chk = 0; chk < KCH; chk++) {
        const int rem = KCH - 1 - chk;
        if (rem >= 2)      asm volatile("cp.async.wait_group 2;" ::: "memory");
        else if (rem == 1) asm volatile("cp.async.wait_group 1;" ::: "memory");
        else               asm volatile("cp.async.wait_group 0;" ::: "memory");
        __syncthreads();

        const uint32_t base = sb + (chk % NSTG) * STG_B;
#pragma unroll
        for (int ks = 0; ks < 4; ks++) {
            uint32_t ah[4][4], bf[2][4];
            const int ca = ks * 2 + a_hk;
            const int cb = ks * 2 + b_ch;
#pragma unroll
            for (int mt = 0; mt < 4; mt++)
                ldsm_x4(ah[mt], base + a_off[mt] + (uint32_t)(((ca ^ a_sel[mt])) << 4));
#pragma unroll
            for (int ntp = 0; ntp < 2; ntp++)
                ldsm_x4(bf[ntp], base + TILE_B + b_off[ntp] + (uint32_t)(((cb ^ b_sel2[ntp])) << 4));
#pragma unroll
            for (int mt = 0; mt < 4; mt++)
#pragma unroll
                for (int nt = 0; nt < 4; nt++)
                    mma16816(c[mt][nt], ah[mt], &bf[nt >> 1][(nt & 1) * 2]);
        }

        if (chk + 3 < KCH) load_stage((chk + 3) % NSTG, (chk + 3) * BK);
    }

    const int t4 = lane >> 2;
    const int t2 = (lane & 3) * 2;
#pragma unroll
    for (int mt = 0; mt < 4; mt++) {
        const int r0 = by * BM + wr * 64 + mt * 16 + t4;
        const int r1 = r0 + 8;
#pragma unroll
        for (int nt = 0; nt < 4; nt++) {
            const int col = bx * BN + wc * 32 + nt * 8 + t2;
            const float bi0 = bias[col], bi1 = bias[col + 1];
            float2 v0 = {c[mt][nt][0] + bi0, c[mt][nt][1] + bi1};
            float2 v1 = {c[mt][nt][2] + bi0, c[mt][nt][3] + bi1};
            *(float2*)(out + (size_t)r0 * CC + col) = v0;
            *(float2*)(out + (size_t)r1 * CC + col) = v1;
        }
    }
}

// ---------------------------------------------------------------------------
// Tensor-core flash attention, fp16, exp2 domain.
// Grid: (T/128, B*H). 256 threads = 8 warps x 16 query rows.
// Q split (2-pass QK), K single, P single (1-pass PV), V single.
// KV tiles of 64, double-buffered cp.async. Output: single fp16 (b,t,c).
// Smem: Qh[0:32K], Ql[32K:64K], stage s at 64K + 32K*s: {K:0, V:16K}.
// ---------------------------------------------------------------------------
static constexpr unsigned ATT_SMEM = 131072;

__global__ __launch_bounds__(256, 1)
void attn_tc_kernel(const __half* __restrict__ qh, const __half* __restrict__ ql,
                    const __half* __restrict__ kh, const __half* __restrict__ vh,
                    const float* __restrict__ mask,
                    __half* __restrict__ outp)
{
    extern __shared__ char smem[];
    const uint32_t sb = smem_u32(smem);
    const int tid = threadIdx.x, lane = tid & 31, warp = tid >> 5;
    const int qb = gridDim.x - 1 - blockIdx.x;     // long CTAs first
    const int bh = blockIdx.y;
    const int b = bh >> 4, h = bh & 15;
    const int q0 = qb * 128;
    const int jmax = 2 * qb + 2;
    const size_t bhoff = (size_t)bh * TT * HD;

    // ---- Q tile load (hi + lo) ----
    {
        const __half* s0 = qh + bhoff + (size_t)q0 * HD;
        const __half* s1 = ql + bhoff + (size_t)q0 * HD;
#pragma unroll
        for (int i = 0; i < 8; i++) {
            const int idx = tid + i * 256;
            const int r = idx >> 4, ch = idx & 15;
            const uint32_t off = r * 256 + ((ch ^ (r & 7)) << 4);
            cp16(sb + off,         s0 + (size_t)r * HD + ch * 8);
            cp16(sb + 32768 + off, s1 + (size_t)r * HD + ch * 8);
        }
        asm volatile("cp.async.commit_group;" ::: "memory");
    }

    auto loadKV = [&](int j, int st) {
        const uint32_t base = sb + 65536 + st * 32768;
        const int kv0 = j * 64;
        const __half* srcs[2] = {
            kh + bhoff + (size_t)kv0 * HD, vh + bhoff + (size_t)kv0 * HD };
#pragma unroll
        for (int i = 0; i < 8; i++) {
            const int idx = tid + i * 256;
            const int mat = idx >> 10, r = (idx >> 4) & 63, ch = idx & 15;
            cp16(base + mat * 16384 + r * 256 + ((ch ^ (r & 7)) << 4),
                 srcs[mat] + (size_t)r * HD + ch * 8);
        }
        asm volatile("cp.async.commit_group;" ::: "memory");
    };

    loadKV(0, 0);
    loadKV(1, 1);

    float o[16][4];
#pragma unroll
    for (int n = 0; n < 16; n++)
#pragma unroll
        for (int i = 0; i < 4; i++) o[n][i] = 0.f;
    float m0 = -1e30f, m1 = -1e30f, l0 = 0.f, l1 = 0.f;

    const int qrow  = warp * 16 + (lane & 15);
    const uint32_t a_base = qrow * 256;
    const int a_sel = qrow & 7;
    const int a_kh  = lane >> 4;
    const int kb_rloc = ((lane >> 4) << 3) + (lane & 7);
    const int kb_ch   = (lane >> 3) & 1;
    const int v_rloc  = lane & 15;
    const int v_chh   = lane >> 4;

    const int qg0 = q0 + warp * 16 + (lane >> 2);
    const int qg1 = qg0 + 8;

    for (int j = 0; j < jmax; j++) {
        const int kv0 = j * 64;
        const int st = j & 1;
        if (j + 1 < jmax) asm volatile("cp.async.wait_group 1;" ::: "memory");
        else              asm volatile("cp.async.wait_group 0;" ::: "memory");
        __syncthreads();

        const uint32_t KB = sb + 65536 + st * 32768;
        const uint32_t VB = KB + 16384;

        // ---- S = Q K^T (2 split passes, Q exact), 16x64 per warp ----
        float s[8][4];
#pragma unroll
        for (int n = 0; n < 8; n++)
#pragma unroll
            for (int i = 0; i < 4; i++) s[n][i] = 0.f;

#pragma unroll
        for (int ks = 0; ks < 8; ks++) {
            uint32_t qfh[4], qfl[4];
            const uint32_t ca = (uint32_t)(((2 * ks + a_kh) ^ a_sel) << 4);
            ldsm_x4(qfh, sb + a_base + ca);
            ldsm_x4(qfl, sb + 32768 + a_base + ca);
            uint32_t kf[16];
#pragma unroll
            for (int i = 0; i < 4; i++) {
                const int r = 16 * i + kb_rloc;
                const uint32_t off = r * 256 + (((2 * ks + kb_ch) ^ (r & 7)) << 4);
                ldsm_x4(&kf[4 * i], KB + off);
            }
#pragma unroll
            for (int n = 0; n < 8; n++) {
                mma16816(s[n], qfh, &kf[2 * n]);
                mma16816(s[n], qfl, &kf[2 * n]);
            }
        }

        // ---- mask + causal ----
        const bool need_mask = (j >= 2 * qb);
#pragma unroll
        for (int n = 0; n < 8; n++) {
            const int kg = kv0 + 8 * n + 2 * (lane & 3);
            const float2 mv = *(const float2*)&mask[b * TT + kg];
            const float am0 = mv.x * LOG2E, am1 = mv.y * LOG2E;
            s[n][0] += am0; s[n][1] += am1;
            s[n][2] += am0; s[n][3] += am1;
            if (need_mask) {
                if (kg     > qg0) s[n][0] = -1e30f;
                if (kg + 1 > qg0) s[n][1] = -1e30f;
                if (kg     > qg1) s[n][2] = -1e30f;
                if (kg + 1 > qg1) s[n][3] = -1e30f;
            }
        }

        // ---- online softmax (quad-local) ----
        float mx0 = m0, mx1 = m1;
#pragma unroll
        for (int n = 0; n < 8; n++) {
            mx0 = fmaxf(mx0, fmaxf(s[n][0], s[n][1]));
            mx1 = fmaxf(mx1, fmaxf(s[n][2], s[n][3]));
        }
        mx0 = fmaxf(mx0, __shfl_xor_sync(0xffffffffu, mx0, 1));
        mx0 = fmaxf(mx0, __shfl_xor_sync(0xffffffffu, mx0, 2));
        mx1 = fmaxf(mx1, __shfl_xor_sync(0xffffffffu, mx1, 1));
        mx1 = fmaxf(mx1, __shfl_xor_sync(0xffffffffu, mx1, 2));
        const float al0 = exp2f(m0 - mx0);
        const float al1 = exp2f(m1 - mx1);
        m0 = mx0; m1 = mx1;
        float sum0 = 0.f, sum1 = 0.f;
#pragma unroll
        for (int n = 0; n < 8; n++) {
            s[n][0] = exp2f(s[n][0] - m0);
            s[n][1] = exp2f(s[n][1] - m0);
            s[n][2] = exp2f(s[n][2] - m1);
            s[n][3] = exp2f(s[n][3] - m1);
            sum0 += s[n][0] + s[n][1];
            sum1 += s[n][2] + s[n][3];
        }
        sum0 += __shfl_xor_sync(0xffffffffu, sum0, 1);
        sum0 += __shfl_xor_sync(0xffffffffu, sum0, 2);
        sum1 += __shfl_xor_sync(0xffffffffu, sum1, 1);
        sum1 += __shfl_xor_sync(0xffffffffu, sum1, 2);
        l0 = l0 * al0 + sum0;
        l1 = l1 * al1 + sum1;
#pragma unroll
        for (int n = 0; n < 16; n++) {
            o[n][0] *= al0; o[n][1] *= al0;
            o[n][2] *= al1; o[n][3] *= al1;
        }

        // ---- O += P V (register repack, P single, 1 pass) ----
#pragma unroll
        for (int kv = 0; kv < 4; kv++) {
            uint32_t pa[4];
            pa[0] = pack_h2(s[2 * kv][0],     s[2 * kv][1]);
            pa[1] = pack_h2(s[2 * kv][2],     s[2 * kv][3]);
            pa[2] = pack_h2(s[2 * kv + 1][0], s[2 * kv + 1][1]);
            pa[3] = pack_h2(s[2 * kv + 1][2], s[2 * kv + 1][3]);
            const int vr = 16 * kv + v_rloc;
            const uint32_t vro = vr * 256;
            const int vsel = vr & 7;
#pragma unroll
            for (int i = 0; i < 8; i++) {
                const uint32_t ch = (uint32_t)(((2 * i + v_chh) ^ vsel) << 4);
                uint32_t vf[4];
                ldsm_x4t(vf, VB + vro + ch);
                mma16816(o[2 * i],     pa, &vf[0]);
                mma16816(o[2 * i + 1], pa, &vf[2]);
            }
        }

        __syncthreads();
        if (j + 2 < jmax) loadKV(j + 2, st);
    }

    // ---- epilogue: normalize, single fp16, write (b,t,c) ----
    const float inv0 = 1.f / l0, inv1 = 1.f / l1;
    const size_t r0base = ((size_t)b * TT + qg0) * CC + h * HD;
    const size_t r1base = ((size_t)b * TT + qg1) * CC + h * HD;
#pragma unroll
    for (int n = 0; n < 16; n++) {
        const int d = 8 * n + 2 * (lane & 3);
        *(uint32_t*)&outp[r0base + d] = pack_h2(o[n][0] * inv0, o[n][1] * inv0);
        *(uint32_t*)&outp[r1base + d] = pack_h2(o[n][2] * inv1, o[n][3] * inv1);
    }
}

// ---------------------------------------------------------------------------
// Launcher
// ---------------------------------------------------------------------------
extern "C" void kernel_launch(void* const* d_in, const int* in_sizes, int n_in,
                              void* d_out, int out_size)
{
    const float* x    = (const float*)d_in[0];
    const float* mask = (const float*)d_in[1];
    const float* bq   = (const float*)d_in[3];
    const float* bk   = (const float*)d_in[5];
    const float* bv   = (const float*)d_in[7];
    const float* bp   = (const float*)d_in[9];
    float* out = (float*)d_out;

    __half *xp, *at, *w, *qh, *ql, *kh, *vhp;
    cudaGetSymbolAddress((void**)&xp,  g_x);
    cudaGetSymbolAddress((void**)&at,  g_at);
    cudaGetSymbolAddress((void**)&w,   g_w);
    cudaGetSymbolAddress((void**)&qh,  g_qh);
    cudaGetSymbolAddress((void**)&ql,  g_ql);
    cudaGetSymbolAddress((void**)&kh,  g_kh);
    cudaGetSymbolAddress((void**)&vhp, g_vh);

    cudaFuncSetAttribute(gemm_qkv_kernel,
                         cudaFuncAttributeMaxDynamicSharedMemorySize, GEMM_SMEM);
    cudaFuncSetAttribute(gemm1_tc_kernel,
                         cudaFuncAttributeMaxDynamicSharedMemorySize, GEMM_SMEM);
    cudaFuncSetAttribute(attn_tc_kernel,
                         cudaFuncAttributeMaxDynamicSharedMemorySize, ATT_SMEM);

    // 1. convert x and weights to fp16
    {
        const int n4x = (BB * TT * CC) / 4;
        conv_kernel<<<(n4x / 2 + 255) / 256, 256>>>(x, xp, n4x);
        const int n4w = CC * CC;          // total float4s over 4 matrices
        conv4_kernel<<<(n4w / 2 + 255) / 256, 256>>>(
            (const float*)d_in[2], (const float*)d_in[4],
            (const float*)d_in[6], (const float*)d_in[8], w);
    }

    // 2. fused QKV projection (1-pass; Q split + pre-scaled; K,V single fp16)
    gemm_qkv_kernel<<<dim3(48, MROWS / BM), 256, GEMM_SMEM>>>(
        xp, w, bq, bk, bv, qh, ql, kh, vhp);

    // 3. flash attention -> single fp16 (b,t,c)
    attn_tc_kernel<<<dim3(TT / 128, BB * NH), 256, ATT_SMEM>>>(
        qh, ql, kh, vhp, mask, at);

    // 4. output projection (1-pass) -> fp32 out
    gemm1_tc_kernel<<<dim3(CC / BN, MROWS / BM), 256, GEMM_SMEM>>>(
        at, w + 3 * (size_t)CC * CC, bp, out);
}

// round 16
// speedup vs baseline: 1.5021x; 1.0409x over previous
#include <cuda_runtime.h>
#include <cuda_fp16.h>
#include <math.h>
#include <stdint.h>
#include <stddef.h>

// Problem constants
#define BB   4
#define TT   2048
#define CC   2048
#define NH   16
#define HD   128
#define MROWS (BB * TT)          // 8192
#define LOG2E 1.4426950408889634f
#define QSCALE 0.12751743502016435f   // (1/sqrt(128)) * log2(e)

// ---------------------------------------------------------------------------
// Scratch (device globals)
// ---------------------------------------------------------------------------
__device__ __half g_x[BB * TT * CC];       // x single fp16
__device__ __half g_at[BB * TT * CC];      // attention out, single fp16
__device__ __half g_w[4][CC * CC];         // weights, single fp16
__device__ __half g_qh[BB * NH * TT * HD]; // (b,h,t,d) Q split hi
__device__ __half g_ql[BB * NH * TT * HD]; // Q split lo
__device__ __half g_kh[BB * NH * TT * HD]; // K single fp16
__device__ __half g_vh[BB * NH * TT * HD]; // V single fp16

// ---------------------------------------------------------------------------
// Helpers
// ---------------------------------------------------------------------------
__device__ __forceinline__ uint32_t smem_u32(const void* p) {
    uint32_t a;
    asm("{ .reg .u64 t; cvta.to.shared.u64 t, %1; cvt.u32.u64 %0, t; }"
        : "=r"(a) : "l"(p));
    return a;
}
__device__ __forceinline__ void cp16(uint32_t dst, const void* src) {
    asm volatile("cp.async.cg.shared.global [%0], [%1], 16;"
                 :: "r"(dst), "l"(src) : "memory");
}
__device__ __forceinline__ void ldsm_x4(uint32_t* r, uint32_t addr) {
    asm volatile("ldmatrix.sync.aligned.m8n8.x4.shared.b16 {%0,%1,%2,%3}, [%4];"
        : "=r"(r[0]), "=r"(r[1]), "=r"(r[2]), "=r"(r[3]) : "r"(addr));
}
__device__ __forceinline__ void ldsm_x4t(uint32_t* r, uint32_t addr) {
    asm volatile("ldmatrix.sync.aligned.m8n8.x4.trans.shared.b16 {%0,%1,%2,%3}, [%4];"
        : "=r"(r[0]), "=r"(r[1]), "=r"(r[2]), "=r"(r[3]) : "r"(addr));
}
// fp16 MMA m16n8k16, fp32 accumulate
__device__ __forceinline__ void mma16816(float* c, const uint32_t* a, const uint32_t* b) {
    asm volatile("mma.sync.aligned.m16n8k16.row.col.f32.f16.f16.f32 "
        "{%0,%1,%2,%3}, {%4,%5,%6,%7}, {%8,%9}, {%0,%1,%2,%3};"
        : "+f"(c[0]), "+f"(c[1]), "+f"(c[2]), "+f"(c[3])
        : "r"(a[0]), "r"(a[1]), "r"(a[2]), "r"(a[3]), "r"(b[0]), "r"(b[1]));
}
// pack (a,b) -> fp16x2 hi word + lo word (a in low half)
__device__ __forceinline__ void split_pack(float a, float b, uint32_t& h, uint32_t& l) {
    __half ah = __float2half_rn(a);
    __half bh = __float2half_rn(b);
    __half2 hh; hh.x = ah; hh.y = bh;
    h = *(uint32_t*)&hh;
    __half2 ll;
    ll.x = __float2half_rn(a - __half2float(ah));
    ll.y = __float2half_rn(b - __half2float(bh));
    l = *(uint32_t*)&ll;
}
__device__ __forceinline__ uint32_t pack_h2(float a, float b) {
    __half2 hh; hh.x = __float2half_rn(a); hh.y = __float2half_rn(b);
    return *(uint32_t*)&hh;
}

// ---------------------------------------------------------------------------
// fp32 -> fp16 converts (ILP 2)
// ---------------------------------------------------------------------------
__global__ void conv_kernel(const float* __restrict__ in,
                            __half* __restrict__ out, int n4)
{
    int i = (blockIdx.x * blockDim.x + threadIdx.x) * 2;
    if (i + 1 >= n4) {
        if (i >= n4) return;
        float4 v = ((const float4*)in)[i];
        __align__(8) __half h[4];
        h[0] = __float2half_rn(v.x); h[1] = __float2half_rn(v.y);
        h[2] = __float2half_rn(v.z); h[3] = __float2half_rn(v.w);
        ((uint2*)out)[i] = *(uint2*)h;
        return;
    }
    float4 v0 = ((const float4*)in)[i];
    float4 v1 = ((const float4*)in)[i + 1];
    __align__(8) __half h0[4], h1[4];
    h0[0] = __float2half_rn(v0.x); h0[1] = __float2half_rn(v0.y);
    h0[2] = __float2half_rn(v0.z); h0[3] = __float2half_rn(v0.w);
    h1[0] = __float2half_rn(v1.x); h1[1] = __float2half_rn(v1.y);
    h1[2] = __float2half_rn(v1.z); h1[3] = __float2half_rn(v1.w);
    ((uint2*)out)[i]     = *(uint2*)h0;
    ((uint2*)out)[i + 1] = *(uint2*)h1;
}

// 4 weight matrices in one launch (dst contiguous), ILP 2
__global__ void conv4_kernel(const float* __restrict__ w0, const float* __restrict__ w1,
                             const float* __restrict__ w2, const float* __restrict__ w3,
                             __half* __restrict__ out)
{
    const int per = (CC * CC) / 4;           // float4s per matrix
    int i = (blockIdx.x * blockDim.x + threadIdx.x) * 2;
    if (i >= 4 * per) return;
#pragma unroll
    for (int u = 0; u < 2; u++) {
        const int idx = i + u;
        const int m = idx / per, r = idx % per;
        const float* src = (m == 0) ? w0 : (m == 1) ? w1 : (m == 2) ? w2 : w3;
        float4 v = ((const float4*)src)[r];
        __align__(8) __half h[4];
        h[0] = __float2half_rn(v.x); h[1] = __float2half_rn(v.y);
        h[2] = __float2half_rn(v.z); h[3] = __float2half_rn(v.w);
        ((uint2*)out)[idx] = *(uint2*)h;
    }
}

// ---------------------------------------------------------------------------
// Common GEMM geometry
// ---------------------------------------------------------------------------
#define BM 128
#define BN 128
#define BK 64
#define KCH (CC / BK)                 // 32
#define TILE_B 16384                  // 128 rows x 128 bytes
#define NSTG 4
#define STG_B (2 * TILE_B)            // A, W
static constexpr unsigned GEMM_SMEM = NSTG * STG_B;   // 131072

// ---------------------------------------------------------------------------
// Fused QKV GEMM (1-pass fp16):
//   grid (48, 64); bx>>4 selects {Q,K,V}; bx&15 = head/N-tile.
//   Q -> split hi/lo (pre-scaled QSCALE); K,V -> single fp16, head layout.
// ---------------------------------------------------------------------------
__global__ __launch_bounds__(256, 1)
void gemm_qkv_kernel(const __half* __restrict__ X,
                     const __half* __restrict__ Wbase,
                     const float* __restrict__ bq,
                     const float* __restrict__ bk,
                     const float* __restrict__ bv,
                     __half* __restrict__ qh, __half* __restrict__ ql,
                     __half* __restrict__ kh, __half* __restrict__ vh)
{
    extern __shared__ char smem[];
    const uint32_t sb = smem_u32(smem);
    const int tid  = threadIdx.x;
    const int lane = tid & 31;
    const int wid  = tid >> 5;
    const int wr   = wid >> 2;
    const int wc   = wid & 3;
    const int bx = blockIdx.x, by = blockIdx.y;
    const int sel = bx >> 4;              // 0=Q, 1=K, 2=V
    const int hx  = bx & 15;              // head / N-tile

    const float* bias = (sel == 0) ? bq : (sel == 1) ? bk : bv;
    const float escale = (sel == 0) ? QSCALE : 1.0f;

    const __half* srcs[2] = {
        X + (size_t)by * BM * CC,
        Wbase + (size_t)sel * CC * CC + (size_t)hx * BN * CC
    };

    auto load_stage = [&](int stg, int kc) {
        const uint32_t base = sb + stg * STG_B;
#pragma unroll
        for (int ti = 0; ti < 2; ti++) {
            const __half* src = srcs[ti];
            const uint32_t tb = base + ti * TILE_B;
#pragma unroll
            for (int i = 0; i < 4; i++) {
                const int idx = tid + i * 256;
                const int row = idx >> 3;
                const int ch  = idx & 7;
                const uint32_t dst = tb + row * 128 + ((ch ^ (row & 7)) << 4);
                cp16(dst, src + (size_t)row * CC + kc + ch * 8);
            }
        }
        asm volatile("cp.async.commit_group;" ::: "memory");
    };

    const int a_lr = lane & 15;
    const int a_hk = lane >> 4;
    uint32_t a_off[4]; int a_sel[4];
#pragma unroll
    for (int mt = 0; mt < 4; mt++) {
        const int r = wr * 64 + mt * 16 + a_lr;
        a_off[mt] = r * 128;
        a_sel[mt] = r & 7;
    }
    const int b_rloc = ((lane >> 4) << 3) + (lane & 7);
    const int b_ch   = (lane >> 3) & 1;
    uint32_t b_off[2]; int b_sel2[2];
#pragma unroll
    for (int ntp = 0; ntp < 2; ntp++) {
        const int r = wc * 32 + ntp * 16 + b_rloc;
        b_off[ntp] = r * 128;
        b_sel2[ntp] = r & 7;
    }

    float c[4][4][4];
#pragma unroll
    for (int mt = 0; mt < 4; mt++)
#pragma unroll
        for (int nt = 0; nt < 4; nt++)
#pragma unroll
            for (int i = 0; i < 4; i++) c[mt][nt][i] = 0.f;

    load_stage(0, 0);
    load_stage(1, BK);
    load_stage(2, 2 * BK);

    for (int chk = 0; chk < KCH; chk++) {
        const int rem = KCH - 1 - chk;
        if (rem >= 2)      asm volatile("cp.async.wait_group 2;" ::: "memory");
        else if (rem == 1) asm volatile("cp.async.wait_group 1;" ::: "memory");
        else               asm volatile("cp.async.wait_group 0;" ::: "memory");
        __syncthreads();

        const uint32_t base = sb + (chk % NSTG) * STG_B;
#pragma unroll
        for (int ks = 0; ks < 4; ks++) {
            uint32_t ah[4][4], bf[2][4];
            const int ca = ks * 2 + a_hk;
            const int cb = ks * 2 + b_ch;
#pragma unroll
            for (int mt = 0; mt < 4; mt++)
                ldsm_x4(ah[mt], base + a_off[mt] + (uint32_t)(((ca ^ a_sel[mt])) << 4));
#pragma unroll
            for (int ntp = 0; ntp < 2; ntp++)
                ldsm_x4(bf[ntp], base + TILE_B + b_off[ntp] + (uint32_t)(((cb ^ b_sel2[ntp])) << 4));
#pragma unroll
            for (int mt = 0; mt < 4; mt++)
#pragma unroll
                for (int nt = 0; nt < 4; nt++)
                    mma16816(c[mt][nt], ah[mt], &bf[nt >> 1][(nt & 1) * 2]);
        }

        if (chk + 3 < KCH) load_stage((chk + 3) % NSTG, (chk + 3) * BK);
    }

    // ---- epilogue (head layout) ----
    const int t4 = lane >> 2;
    const int t2 = (lane & 3) * 2;
#pragma unroll
    for (int mt = 0; mt < 4; mt++) {
        const int r0 = by * BM + wr * 64 + mt * 16 + t4;
        const int r1 = r0 + 8;
#pragma unroll
        for (int nt = 0; nt < 4; nt++) {
            const int col = hx * BN + wc * 32 + nt * 8 + t2;
            const float bi0 = bias[col], bi1 = bias[col + 1];
            const float v00 = (c[mt][nt][0] + bi0) * escale;
            const float v01 = (c[mt][nt][1] + bi1) * escale;
            const float v10 = (c[mt][nt][2] + bi0) * escale;
            const float v11 = (c[mt][nt][3] + bi1) * escale;
            const int d = col & 127;
            const int b0 = r0 >> 11, t0 = r0 & 2047;
            const int b1 = r1 >> 11, t1 = r1 & 2047;
            const size_t i0 = (((size_t)(b0 * NH + hx)) * TT + t0) * HD + d;
            const size_t i1 = (((size_t)(b1 * NH + hx)) * TT + t1) * HD + d;
            if (sel == 0) {
                uint32_t ph, pl;
                split_pack(v00, v01, ph, pl);
                *(uint32_t*)&qh[i0] = ph; *(uint32_t*)&ql[i0] = pl;
                split_pack(v10, v11, ph, pl);
                *(uint32_t*)&qh[i1] = ph; *(uint32_t*)&ql[i1] = pl;
            } else {
                __half* o = (sel == 1) ? kh : vh;
                *(uint32_t*)&o[i0] = pack_h2(v00, v01);
                *(uint32_t*)&o[i1] = pack_h2(v10, v11);
            }
        }
    }
}

// ---------------------------------------------------------------------------
// 1-pass fp16 GEMM (output projection): out = att @ Wp^T + bp, fp32 out.
// grid (16, 64).
// ---------------------------------------------------------------------------
__global__ __launch_bounds__(256, 1)
void gemm1_tc_kernel(const __half* __restrict__ A,
                     const __half* __restrict__ W,
                     const float* __restrict__ bias,
                     float* __restrict__ out)
{
    extern __shared__ char smem[];
    const uint32_t sb = smem_u32(smem);
    const int tid  = threadIdx.x;
    const int lane = tid & 31;
    const int wid  = tid >> 5;
    const int wr   = wid >> 2;
    const int wc   = wid & 3;
    const int bx = blockIdx.x, by = blockIdx.y;

    const __half* srcs[2] = {
        A + (size_t)by * BM * CC,
        W + (size_t)bx * BN * CC
    };

    auto load_stage = [&](int stg, int kc) {
        const uint32_t base = sb + stg * STG_B;
#pragma unroll
        for (int ti = 0; ti < 2; ti++) {
            const __half* src = srcs[ti];
            const uint32_t tb = base + ti * TILE_B;
#pragma unroll
            for (int i = 0; i < 4; i++) {
                const int idx = tid + i * 256;
                const int row = idx >> 3;
                const int ch  = idx & 7;
                const uint32_t dst = tb + row * 128 + ((ch ^ (row & 7)) << 4);
                cp16(dst, src + (size_t)row * CC + kc + ch * 8);
            }
        }
        asm volatile("cp.async.commit_group;" ::: "memory");
    };

    const int a_lr = lane & 15;
    const int a_hk = lane >> 4;
    uint32_t a_off[4]; int a_sel[4];
#pragma unroll
    for (int mt = 0; mt < 4; mt++) {
        const int r = wr * 64 + mt * 16 + a_lr;
        a_off[mt] = r * 128;
        a_sel[mt] = r & 7;
    }
    const int b_rloc = ((lane >> 4) << 3) + (lane & 7);
    const int b_ch   = (lane >> 3) & 1;
    uint32_t b_off[2]; int b_sel2[2];
#pragma unroll
    for (int ntp = 0; ntp < 2; ntp++) {
        const int r = wc * 32 + ntp * 16 + b_rloc;
        b_off[ntp] = r * 128;
        b_sel2[ntp] = r & 7;
    }

    float c[4][4][4];
#pragma unroll
    for (int mt = 0; mt < 4; mt++)
#pragma unroll
        for (int nt = 0; nt < 4; nt++)
#pragma unroll
            for (int i = 0; i < 4; i++) c[mt][nt][i] = 0.f;

    load_stage(0, 0);
    load_stage(1, BK);
    load_stage(2, 2 * BK);

    for (int chk = 0; chk < KCH; chk++) {
        const int rem = KCH - 1 - chk;
        if (rem >= 2)      asm volatile("cp.async.wait_group 2;" ::: "memory");
        else if (rem == 1) asm volatile("cp.async.wait_group 1;" ::: "memory");
        else               asm volatile("cp.async.wait_group 0;" ::: "memory");
        __syncthreads();

        const uint32_t base = sb + (chk % NSTG) * STG_B;
#pragma unroll
        for (int ks = 0; ks < 4; ks++) {
            uint32_t ah[4][4], bf[2][4];
            const int ca = ks * 2 + a_hk;
            const int cb = ks * 2 + b_ch;
#pragma unroll
            for (int mt = 0; mt < 4; mt++)
                ldsm_x4(ah[mt], base + a_off[mt] + (uint32_t)(((ca ^ a_sel[mt])) << 4));
#pragma unroll
            for (int ntp = 0; ntp < 2; ntp++)
                ldsm_x4(bf[ntp], base + TILE_B + b_off[ntp] + (uint32_t)(((cb ^ b_sel2[ntp])) << 4));
#pragma unroll
            for (int mt = 0; mt < 4; mt++)
#pragma unroll
                for (int nt = 0; nt < 4; nt++)
                    mma16816(c[mt][nt], ah[mt], &bf[nt >> 1][(nt & 1) * 2]);
        }

        if (chk + 3 < KCH) load_stage((chk + 3) % NSTG, (chk + 3) * BK);
    }

    const int t4 = lane >> 2;
    const int t2 = (lane & 3) * 2;
#pragma unroll
    for (int mt = 0; mt < 4; mt++) {
        const int r0 = by * BM + wr * 64 + mt * 16 + t4;
        const int r1 = r0 + 8;
#pragma unroll
        for (int nt = 0; nt < 4; nt++) {
            const int col = bx * BN + wc * 32 + nt * 8 + t2;
            const float bi0 = bias[col], bi1 = bias[col + 1];
            float2 v0 = {c[mt][nt][0] + bi0, c[mt][nt][1] + bi1};
            float2 v1 = {c[mt][nt][2] + bi0, c[mt][nt][3] + bi1};
            *(float2*)(out + (size_t)r0 * CC + col) = v0;
            *(float2*)(out + (size_t)r1 * CC + col) = v1;
        }
    }
}

// ---------------------------------------------------------------------------
// Tensor-core flash attention, fp16, exp2 domain.
// Grid: (T/64, B*H). 128 threads = 4 warps x 16 query rows (64-query tile).
// 2 CTAs/SM (regs + 96KB smem fit) for cross-CTA latency hiding.
// Q split (2-pass QK), K single, P single (1-pass PV), V single.
// KV tiles of 64, double-buffered cp.async. Output: single fp16 (b,t,c).
// Smem: Qh[0:16K], Ql[16K:32K], stage s at 32K + 32K*s: {K:0, V:16K}.
// ---------------------------------------------------------------------------
static constexpr unsigned ATT_SMEM = 98304;   // 96 KB

__global__ __launch_bounds__(128, 2)
void attn_tc_kernel(const __half* __restrict__ qh, const __half* __restrict__ ql,
                    const __half* __restrict__ kh, const __half* __restrict__ vh,
                    const float* __restrict__ mask,
                    __half* __restrict__ outp)
{
    extern __shared__ char smem[];
    const uint32_t sb = smem_u32(smem);
    const int tid = threadIdx.x, lane = tid & 31, warp = tid >> 5;
    const int qb = gridDim.x - 1 - blockIdx.x;     // long CTAs first
    const int bh = blockIdx.y;
    const int b = bh >> 4, h = bh & 15;
    const int q0 = qb * 64;
    const int jmax = qb + 1;
    const size_t bhoff = (size_t)bh * TT * HD;

    // ---- Q tile load (hi + lo): 64 rows x 256B each ----
    {
        const __half* s0 = qh + bhoff + (size_t)q0 * HD;
        const __half* s1 = ql + bhoff + (size_t)q0 * HD;
#pragma unroll
        for (int i = 0; i < 8; i++) {
            const int idx = tid + i * 128;          // 1024 chunks per matrix
            const int r = idx >> 4, ch = idx & 15;
            const uint32_t off = r * 256 + ((ch ^ (r & 7)) << 4);
            cp16(sb + off,         s0 + (size_t)r * HD + ch * 8);
            cp16(sb + 16384 + off, s1 + (size_t)r * HD + ch * 8);
        }
        asm volatile("cp.async.commit_group;" ::: "memory");
    }

    auto loadKV = [&](int j, int st) {
        const uint32_t base = sb + 32768 + st * 32768;
        const int kv0 = j * 64;
        const __half* srcs[2] = {
            kh + bhoff + (size_t)kv0 * HD, vh + bhoff + (size_t)kv0 * HD };
#pragma unroll
        for (int i = 0; i < 16; i++) {
            const int idx = tid + i * 128;          // 2048 chunks
            const int mat = idx >> 10, r = (idx >> 4) & 63, ch = idx & 15;
            cp16(base + mat * 16384 + r * 256 + ((ch ^ (r & 7)) << 4),
                 srcs[mat] + (size_t)r * HD + ch * 8);
        }
        asm volatile("cp.async.commit_group;" ::: "memory");
    };

    // tile 1 prefetch is safe even when jmax==1 (rows 64..127 < T)
    loadKV(0, 0);
    loadKV(1, 1);

    float o[16][4];
#pragma unroll
    for (int n = 0; n < 16; n++)
#pragma unroll
        for (int i = 0; i < 4; i++) o[n][i] = 0.f;
    float m0 = -1e30f, m1 = -1e30f, l0 = 0.f, l1 = 0.f;

    const int qrow  = warp * 16 + (lane & 15);
    const uint32_t a_base = qrow * 256;
    const int a_sel = qrow & 7;
    const int a_kh  = lane >> 4;
    const int kb_rloc = ((lane >> 4) << 3) + (lane & 7);
    const int kb_ch   = (lane >> 3) & 1;
    const int v_rloc  = lane & 15;
    const int v_chh   = lane >> 4;

    const int qg0 = q0 + warp * 16 + (lane >> 2);
    const int qg1 = qg0 + 8;

    for (int j = 0; j < jmax; j++) {
        const int kv0 = j * 64;
        const int st = j & 1;
        if (j + 1 < jmax) asm volatile("cp.async.wait_group 1;" ::: "memory");
        else              asm volatile("cp.async.wait_group 0;" ::: "memory");
        __syncthreads();

        const uint32_t KB = sb + 32768 + st * 32768;
        const uint32_t VB = KB + 16384;

        // ---- S = Q K^T (2 split passes, Q exact), 16x64 per warp ----
        float s[8][4];
#pragma unroll
        for (int n = 0; n < 8; n++)
#pragma unroll
            for (int i = 0; i < 4; i++) s[n][i] = 0.f;

#pragma unroll
        for (int ks = 0; ks < 8; ks++) {
            uint32_t qfh[4], qfl[4];
            const uint32_t ca = (uint32_t)(((2 * ks + a_kh) ^ a_sel) << 4);
            ldsm_x4(qfh, sb + a_base + ca);
            ldsm_x4(qfl, sb + 16384 + a_base + ca);
            uint32_t kf[16];
#pragma unroll
            for (int i = 0; i < 4; i++) {
                const int r = 16 * i + kb_rloc;
                const uint32_t off = r * 256 + (((2 * ks + kb_ch) ^ (r & 7)) << 4);
                ldsm_x4(&kf[4 * i], KB + off);
            }
#pragma unroll
            for (int n = 0; n < 8; n++) {
                mma16816(s[n], qfh, &kf[2 * n]);
                mma16816(s[n], qfl, &kf[2 * n]);
            }
        }

        // ---- mask + causal (diagonal tile only) ----
        const bool need_mask = (j == qb);
#pragma unroll
        for (int n = 0; n < 8; n++) {
            const int kg = kv0 + 8 * n + 2 * (lane & 3);
            const float2 mv = *(const float2*)&mask[b * TT + kg];
            const float am0 = mv.x * LOG2E, am1 = mv.y * LOG2E;
            s[n][0] += am0; s[n][1] += am1;
            s[n][2] += am0; s[n][3] += am1;
            if (need_mask) {
                if (kg     > qg0) s[n][0] = -1e30f;
                if (kg + 1 > qg0) s[n][1] = -1e30f;
                if (kg     > qg1) s[n][2] = -1e30f;
                if (kg + 1 > qg1) s[n][3] = -1e30f;
            }
        }

        // ---- online softmax (quad-local) ----
        float mx0 = m0, mx1 = m1;
#pragma unroll
        for (int n = 0; n < 8; n++) {
            mx0 = fmaxf(mx0, fmaxf(s[n][0], s[n][1]));
            mx1 = fmaxf(mx1, fmaxf(s[n][2], s[n][3]));
        }
        mx0 = fmaxf(mx0, __shfl_xor_sync(0xffffffffu, mx0, 1));
        mx0 = fmaxf(mx0, __shfl_xor_sync(0xffffffffu, mx0, 2));
        mx1 = fmaxf(mx1, __shfl_xor_sync(0xffffffffu, mx1, 1));
        mx1 = fmaxf(mx1, __shfl_xor_sync(0xffffffffu, mx1, 2));
        const float al0 = exp2f(m0 - mx0);
        const float al1 = exp2f(m1 - mx1);
        m0 = mx0; m1 = mx1;
        float sum0 = 0.f, sum1 = 0.f;
#pragma unroll
        for (int n = 0; n < 8; n++) {
            s[n][0] = exp2f(s[n][0] - m0);
            s[n][1] = exp2f(s[n][1] - m0);
            s[n][2] = exp2f(s[n][2] - m1);
            s[n][3] = exp2f(s[n][3] - m1);
            sum0 += s[n][0] + s[n][1];
            sum1 += s[n][2] + s[n][3];
        }
        sum0 += __shfl_xor_sync(0xffffffffu, sum0, 1);
        sum0 += __shfl_xor_sync(0xffffffffu, sum0, 2);
        sum1 += __shfl_xor_sync(0xffffffffu, sum1, 1);
        sum1 += __shfl_xor_sync(0xffffffffu, sum1, 2);
        l0 = l0 * al0 + sum0;
        l1 = l1 * al1 + sum1;
#pragma unroll
        for (int n = 0; n < 16; n++) {
            o[n][0] *= al0; o[n][1] *= al0;
            o[n][2] *= al1; o[n][3] *= al1;
        }

        // ---- O += P V (register repack, P single, 1 pass) ----
#pragma unroll
        for (int kv = 0; kv < 4; kv++) {
            uint32_t pa[4];
            pa[0] = pack_h2(s[2 * kv][0],     s[2 * kv][1]);
            pa[1] = pack_h2(s[2 * kv][2],     s[2 * kv][3]);
            pa[2] = pack_h2(s[2 * kv + 1][0], s[2 * kv + 1][1]);
            pa[3] = pack_h2(s[2 * kv + 1][2], s[2 * kv + 1][3]);
            const int vr = 16 * kv + v_rloc;
            const uint32_t vro = vr * 256;
            const int vsel = vr & 7;
#pragma unroll
            for (int i = 0; i < 8; i++) {
                const uint32_t ch = (uint32_t)(((2 * i + v_chh) ^ vsel) << 4);
                uint32_t vf[4];
                ldsm_x4t(vf, VB + vro + ch);
                mma16816(o[2 * i],     pa, &vf[0]);
                mma16816(o[2 * i + 1], pa, &vf[2]);
            }
        }

        __syncthreads();
        if (j + 2 < jmax) loadKV(j + 2, st);
    }

    // ---- epilogue: normalize, single fp16, write (b,t,c) ----
    const float inv0 = 1.f / l0, inv1 = 1.f / l1;
    const size_t r0base = ((size_t)b * TT + qg0) * CC + h * HD;
    const size_t r1base = ((size_t)b * TT + qg1) * CC + h * HD;
#pragma unroll
    for (int n = 0; n < 16; n++) {
        const int d = 8 * n + 2 * (lane & 3);
        *(uint32_t*)&outp[r0base + d] = pack_h2(o[n][0] * inv0, o[n][1] * inv0);
        *(uint32_t*)&outp[r1base + d] = pack_h2(o[n][2] * inv1, o[n][3] * inv1);
    }
}

// ---------------------------------------------------------------------------
// Launcher
// ---------------------------------------------------------------------------
extern "C" void kernel_launch(void* const* d_in, const int* in_sizes, int n_in,
                              void* d_out, int out_size)
{
    const float* x    = (const float*)d_in[0];
    const float* mask = (const float*)d_in[1];
    const float* bq   = (const float*)d_in[3];
    const float* bk   = (const float*)d_in[5];
    const float* bv   = (const float*)d_in[7];
    const float* bp   = (const float*)d_in[9];
    float* out = (float*)d_out;

    __half *xp, *at, *w, *qh, *ql, *kh, *vhp;
    cudaGetSymbolAddress((void**)&xp,  g_x);
    cudaGetSymbolAddress((void**)&at,  g_at);
    cudaGetSymbolAddress((void**)&w,   g_w);
    cudaGetSymbolAddress((void**)&qh,  g_qh);
    cudaGetSymbolAddress((void**)&ql,  g_ql);
    cudaGetSymbolAddress((void**)&kh,  g_kh);
    cudaGetSymbolAddress((void**)&vhp, g_vh);

    cudaFuncSetAttribute(gemm_qkv_kernel,
                         cudaFuncAttributeMaxDynamicSharedMemorySize, GEMM_SMEM);
    cudaFuncSetAttribute(gemm1_tc_kernel,
                         cudaFuncAttributeMaxDynamicSharedMemorySize, GEMM_SMEM);
    cudaFuncSetAttribute(attn_tc_kernel,
                         cudaFuncAttributeMaxDynamicSharedMemorySize, ATT_SMEM);

    // 1. convert x and weights to fp16
    {
        const int n4x = (BB * TT * CC) / 4;
        conv_kernel<<<(n4x / 2 + 255) / 256, 256>>>(x, xp, n4x);
        const int n4w = CC * CC;          // total float4s over 4 matrices
        conv4_kernel<<<(n4w / 2 + 255) / 256, 256>>>(
            (const float*)d_in[2], (const float*)d_in[4],
            (const float*)d_in[6], (const float*)d_in[8], w);
    }

    // 2. fused QKV projection (1-pass; Q split + pre-scaled; K,V single fp16)
    gemm_qkv_kernel<<<dim3(48, MROWS / BM), 256, GEMM_SMEM>>>(
        xp, w, bq, bk, bv, qh, ql, kh, vhp);

    // 3. flash attention -> single fp16 (b,t,c); 64-query CTAs, 2 CTAs/SM
    attn_tc_kernel<<<dim3(TT / 64, BB * NH), 128, ATT_SMEM>>>(
        qh, ql, kh, vhp, mask, at);

    // 4. output projection (1-pass) -> fp32 out
    gemm1_tc_kernel<<<dim3(CC / BN, MROWS / BM), 256, GEMM_SMEM>>>(
        at, w + 3 * (size_t)CC * CC, bp, out);
}

// round 17
// speedup vs baseline: 1.5390x; 1.0246x over previous
#include <cuda_runtime.h>
#include <cuda_fp16.h>
#include <math.h>
#include <stdint.h>
#include <stddef.h>

// Problem constants
#define BB   4
#define TT   2048
#define CC   2048
#define NH   16
#define HD   128
#define MROWS (BB * TT)          // 8192
#define LOG2E 1.4426950408889634f
#define QSCALE 0.12751743502016435f   // (1/sqrt(128)) * log2(e)

// ---------------------------------------------------------------------------
// Scratch (device globals)
// ---------------------------------------------------------------------------
__device__ __half g_x[BB * TT * CC];       // x single fp16
__device__ __half g_at[BB * TT * CC];      // attention out, single fp16
__device__ __half g_w[4][CC * CC];         // weights, single fp16
__device__ __half g_qh[BB * NH * TT * HD]; // (b,h,t,d) Q split hi
__device__ __half g_ql[BB * NH * TT * HD]; // Q split lo
__device__ __half g_kh[BB * NH * TT * HD]; // K single fp16
__device__ __half g_vh[BB * NH * TT * HD]; // V single fp16

// ---------------------------------------------------------------------------
// Helpers
// ---------------------------------------------------------------------------
__device__ __forceinline__ uint32_t smem_u32(const void* p) {
    uint32_t a;
    asm("{ .reg .u64 t; cvta.to.shared.u64 t, %1; cvt.u32.u64 %0, t; }"
        : "=r"(a) : "l"(p));
    return a;
}
__device__ __forceinline__ void cp16(uint32_t dst, const void* src) {
    asm volatile("cp.async.cg.shared.global [%0], [%1], 16;"
                 :: "r"(dst), "l"(src) : "memory");
}
__device__ __forceinline__ void ldsm_x4(uint32_t* r, uint32_t addr) {
    asm volatile("ldmatrix.sync.aligned.m8n8.x4.shared.b16 {%0,%1,%2,%3}, [%4];"
        : "=r"(r[0]), "=r"(r[1]), "=r"(r[2]), "=r"(r[3]) : "r"(addr));
}
__device__ __forceinline__ void ldsm_x4t(uint32_t* r, uint32_t addr) {
    asm volatile("ldmatrix.sync.aligned.m8n8.x4.trans.shared.b16 {%0,%1,%2,%3}, [%4];"
        : "=r"(r[0]), "=r"(r[1]), "=r"(r[2]), "=r"(r[3]) : "r"(addr));
}
// fp16 MMA m16n8k16, fp32 accumulate
__device__ __forceinline__ void mma16816(float* c, const uint32_t* a, const uint32_t* b) {
    asm volatile("mma.sync.aligned.m16n8k16.row.col.f32.f16.f16.f32 "
        "{%0,%1,%2,%3}, {%4,%5,%6,%7}, {%8,%9}, {%0,%1,%2,%3};"
        : "+f"(c[0]), "+f"(c[1]), "+f"(c[2]), "+f"(c[3])
        : "r"(a[0]), "r"(a[1]), "r"(a[2]), "r"(a[3]), "r"(b[0]), "r"(b[1]));
}
// pack (a,b) -> fp16x2 hi word + lo word (a in low half)
__device__ __forceinline__ void split_pack(float a, float b, uint32_t& h, uint32_t& l) {
    __half ah = __float2half_rn(a);
    __half bh = __float2half_rn(b);
    __half2 hh; hh.x = ah; hh.y = bh;
    h = *(uint32_t*)&hh;
    __half2 ll;
    ll.x = __float2half_rn(a - __half2float(ah));
    ll.y = __float2half_rn(b - __half2float(bh));
    l = *(uint32_t*)&ll;
}
__device__ __forceinline__ uint32_t pack_h2(float a, float b) {
    __half2 hh; hh.x = __float2half_rn(a); hh.y = __float2half_rn(b);
    return *(uint32_t*)&hh;
}

// ---------------------------------------------------------------------------
// fp32 -> fp16 converts (ILP 2)
// ---------------------------------------------------------------------------
__global__ void conv_kernel(const float* __restrict__ in,
                            __half* __restrict__ out, int n4)
{
    int i = (blockIdx.x * blockDim.x + threadIdx.x) * 2;
    if (i + 1 >= n4) {
        if (i >= n4) return;
        float4 v = ((const float4*)in)[i];
        __align__(8) __half h[4];
        h[0] = __float2half_rn(v.x); h[1] = __float2half_rn(v.y);
        h[2] = __float2half_rn(v.z); h[3] = __float2half_rn(v.w);
        ((uint2*)out)[i] = *(uint2*)h;
        return;
    }
    float4 v0 = ((const float4*)in)[i];
    float4 v1 = ((const float4*)in)[i + 1];
    __align__(8) __half h0[4], h1[4];
    h0[0] = __float2half_rn(v0.x); h0[1] = __float2half_rn(v0.y);
    h0[2] = __float2half_rn(v0.z); h0[3] = __float2half_rn(v0.w);
    h1[0] = __float2half_rn(v1.x); h1[1] = __float2half_rn(v1.y);
    h1[2] = __float2half_rn(v1.z); h1[3] = __float2half_rn(v1.w);
    ((uint2*)out)[i]     = *(uint2*)h0;
    ((uint2*)out)[i + 1] = *(uint2*)h1;
}

// 4 weight matrices in one launch (dst contiguous), ILP 2
__global__ void conv4_kernel(const float* __restrict__ w0, const float* __restrict__ w1,
                             const float* __restrict__ w2, const float* __restrict__ w3,
                             __half* __restrict__ out)
{
    const int per = (CC * CC) / 4;           // float4s per matrix
    int i = (blockIdx.x * blockDim.x + threadIdx.x) * 2;
    if (i >= 4 * per) return;
#pragma unroll
    for (int u = 0; u < 2; u++) {
        const int idx = i + u;
        const int m = idx / per, r = idx % per;
        const float* src = (m == 0) ? w0 : (m == 1) ? w1 : (m == 2) ? w2 : w3;
        float4 v = ((const float4*)src)[r];
        __align__(8) __half h[4];
        h[0] = __float2half_rn(v.x); h[1] = __float2half_rn(v.y);
        h[2] = __float2half_rn(v.z); h[3] = __float2half_rn(v.w);
        ((uint2*)out)[idx] = *(uint2*)h;
    }
}

// ---------------------------------------------------------------------------
// Common GEMM geometry: 256x128 CTA tile, BK=64, 4-stage cp.async pipeline.
// ---------------------------------------------------------------------------
#define BM 256
#define BN 128
#define BK 64
#define KCH (CC / BK)                 // 32
#define A_TILE_B 32768                // 256 rows x 128 bytes
#define W_TILE_B 16384                // 128 rows x 128 bytes
#define NSTG 4
#define STG_B (A_TILE_B + W_TILE_B)   // 49152
static constexpr unsigned GEMM_SMEM = NSTG * STG_B;   // 196608 (192 KB)

// ---------------------------------------------------------------------------
// Fused QKV GEMM (1-pass fp16), 256x128 tile:
//   grid (48, 32); bx>>4 selects {Q,K,V}; bx&15 = head/N-tile.
//   Q -> split hi/lo (pre-scaled QSCALE); K,V -> single fp16, head layout.
// ---------------------------------------------------------------------------
__global__ __launch_bounds__(256, 1)
void gemm_qkv_kernel(const __half* __restrict__ X,
                     const __half* __restrict__ Wbase,
                     const float* __restrict__ bq,
                     const float* __restrict__ bk,
                     const float* __restrict__ bv,
                     __half* __restrict__ qh, __half* __restrict__ ql,
                     __half* __restrict__ kh, __half* __restrict__ vh)
{
    extern __shared__ char smem[];
    const uint32_t sb = smem_u32(smem);
    const int tid  = threadIdx.x;
    const int lane = tid & 31;
    const int wid  = tid >> 5;
    const int wr   = wid >> 2;            // 0..1 -> 128-row strip
    const int wc   = wid & 3;             // 0..3 -> 32-col strip
    const int bx = blockIdx.x, by = blockIdx.y;
    const int sel = bx >> 4;              // 0=Q, 1=K, 2=V
    const int hx  = bx & 15;              // head / N-tile

    const float* bias = (sel == 0) ? bq : (sel == 1) ? bk : bv;
    const float escale = (sel == 0) ? QSCALE : 1.0f;

    const __half* srcA = X + (size_t)by * BM * CC;
    const __half* srcW = Wbase + (size_t)sel * CC * CC + (size_t)hx * BN * CC;

    auto load_stage = [&](int stg, int kc) {
        const uint32_t base = sb + stg * STG_B;
#pragma unroll
        for (int i = 0; i < 8; i++) {            // A: 2048 chunks
            const int idx = tid + i * 256;
            const int row = idx >> 3;
            const int ch  = idx & 7;
            const uint32_t dst = base + row * 128 + ((ch ^ (row & 7)) << 4);
            cp16(dst, srcA + (size_t)row * CC + kc + ch * 8);
        }
#pragma unroll
        for (int i = 0; i < 4; i++) {            // W: 1024 chunks
            const int idx = tid + i * 256;
            const int row = idx >> 3;
            const int ch  = idx & 7;
            const uint32_t dst = base + A_TILE_B + row * 128 + ((ch ^ (row & 7)) << 4);
            cp16(dst, srcW + (size_t)row * CC + kc + ch * 8);
        }
        asm volatile("cp.async.commit_group;" ::: "memory");
    };

    const int a_lr = lane & 15;
    const int a_hk = lane >> 4;
    uint32_t a_off[8]; int a_sel[8];
#pragma unroll
    for (int mt = 0; mt < 8; mt++) {
        const int r = wr * 128 + mt * 16 + a_lr;
        a_off[mt] = r * 128;
        a_sel[mt] = r & 7;
    }
    const int b_rloc = ((lane >> 4) << 3) + (lane & 7);
    const int b_ch   = (lane >> 3) & 1;
    uint32_t b_off[2]; int b_sel2[2];
#pragma unroll
    for (int ntp = 0; ntp < 2; ntp++) {
        const int r = wc * 32 + ntp * 16 + b_rloc;
        b_off[ntp] = r * 128;
        b_sel2[ntp] = r & 7;
    }

    float c[8][4][4];
#pragma unroll
    for (int mt = 0; mt < 8; mt++)
#pragma unroll
        for (int nt = 0; nt < 4; nt++)
#pragma unroll
            for (int i = 0; i < 4; i++) c[mt][nt][i] = 0.f;

    load_stage(0, 0);
    load_stage(1, BK);
    load_stage(2, 2 * BK);

    for (int chk = 0; chk < KCH; chk++) {
        const int rem = KCH - 1 - chk;
        if (rem >= 2)      asm volatile("cp.async.wait_group 2;" ::: "memory");
        else if (rem == 1) asm volatile("cp.async.wait_group 1;" ::: "memory");
        else               asm volatile("cp.async.wait_group 0;" ::: "memory");
        __syncthreads();

        const uint32_t base = sb + (chk % NSTG) * STG_B;
#pragma unroll
        for (int ks = 0; ks < 4; ks++) {
            uint32_t bf[2][4];
            const int ca = ks * 2 + a_hk;
            const int cb = ks * 2 + b_ch;
#pragma unroll
            for (int ntp = 0; ntp < 2; ntp++)
                ldsm_x4(bf[ntp], base + A_TILE_B + b_off[ntp] + (uint32_t)(((cb ^ b_sel2[ntp])) << 4));
#pragma unroll
            for (int mt = 0; mt < 8; mt++) {
                uint32_t ah[4];
                ldsm_x4(ah, base + a_off[mt] + (uint32_t)(((ca ^ a_sel[mt])) << 4));
#pragma unroll
                for (int nt = 0; nt < 4; nt++)
                    mma16816(c[mt][nt], ah, &bf[nt >> 1][(nt & 1) * 2]);
            }
        }

        if (chk + 3 < KCH) load_stage((chk + 3) % NSTG, (chk + 3) * BK);
    }

    // ---- epilogue (head layout) ----
    const int t4 = lane >> 2;
    const int t2 = (lane & 3) * 2;
#pragma unroll
    for (int mt = 0; mt < 8; mt++) {
        const int r0 = by * BM + wr * 128 + mt * 16 + t4;
        const int r1 = r0 + 8;
#pragma unroll
        for (int nt = 0; nt < 4; nt++) {
            const int col = hx * BN + wc * 32 + nt * 8 + t2;
            const float bi0 = bias[col], bi1 = bias[col + 1];
            const float v00 = (c[mt][nt][0] + bi0) * escale;
            const float v01 = (c[mt][nt][1] + bi1) * escale;
            const float v10 = (c[mt][nt][2] + bi0) * escale;
            const float v11 = (c[mt][nt][3] + bi1) * escale;
            const int d = col & 127;
            const int b0 = r0 >> 11, t0 = r0 & 2047;
            const int b1 = r1 >> 11, t1 = r1 & 2047;
            const size_t i0 = (((size_t)(b0 * NH + hx)) * TT + t0) * HD + d;
            const size_t i1 = (((size_t)(b1 * NH + hx)) * TT + t1) * HD + d;
            if (sel == 0) {
                uint32_t ph, pl;
                split_pack(v00, v01, ph, pl);
                *(uint32_t*)&qh[i0] = ph; *(uint32_t*)&ql[i0] = pl;
                split_pack(v10, v11, ph, pl);
                *(uint32_t*)&qh[i1] = ph; *(uint32_t*)&ql[i1] = pl;
            } else {
                __half* o = (sel == 1) ? kh : vh;
                *(uint32_t*)&o[i0] = pack_h2(v00, v01);
                *(uint32_t*)&o[i1] = pack_h2(v10, v11);
            }
        }
    }
}

// ---------------------------------------------------------------------------
// 1-pass fp16 GEMM (output projection), 256x128 tile: out = att @ Wp^T + bp.
// grid (16, 32).
// ---------------------------------------------------------------------------
__global__ __launch_bounds__(256, 1)
void gemm1_tc_kernel(const __half* __restrict__ A,
                     const __half* __restrict__ W,
                     const float* __restrict__ bias,
                     float* __restrict__ out)
{
    extern __shared__ char smem[];
    const uint32_t sb = smem_u32(smem);
    const int tid  = threadIdx.x;
    const int lane = tid & 31;
    const int wid  = tid >> 5;
    const int wr   = wid >> 2;
    const int wc   = wid & 3;
    const int bx = blockIdx.x, by = blockIdx.y;

    const __half* srcA = A + (size_t)by * BM * CC;
    const __half* srcW = W + (size_t)bx * BN * CC;

    auto load_stage = [&](int stg, int kc) {
        const uint32_t base = sb + stg * STG_B;
#pragma unroll
        for (int i = 0; i < 8; i++) {
            const int idx = tid + i * 256;
            const int row = idx >> 3;
            const int ch  = idx & 7;
            const uint32_t dst = base + row * 128 + ((ch ^ (row & 7)) << 4);
            cp16(dst, srcA + (size_t)row * CC + kc + ch * 8);
        }
#pragma unroll
        for (int i = 0; i < 4; i++) {
            const int idx = tid + i * 256;
            const int row = idx >> 3;
            const int ch  = idx & 7;
            const uint32_t dst = base + A_TILE_B + row * 128 + ((ch ^ (row & 7)) << 4);
            cp16(dst, srcW + (size_t)row * CC + kc + ch * 8);
        }
        asm volatile("cp.async.commit_group;" ::: "memory");
    };

    const int a_lr = lane & 15;
    const int a_hk = lane >> 4;
    uint32_t a_off[8]; int a_sel[8];
#pragma unroll
    for (int mt = 0; mt < 8; mt++) {
        const int r = wr * 128 + mt * 16 + a_lr;
        a_off[mt] = r * 128;
        a_sel[mt] = r & 7;
    }
    const int b_rloc = ((lane >> 4) << 3) + (lane & 7);
    const int b_ch   = (lane >> 3) & 1;
    uint32_t b_off[2]; int b_sel2[2];
#pragma unroll
    for (int ntp = 0; ntp < 2; ntp++) {
        const int r = wc * 32 + ntp * 16 + b_rloc;
        b_off[ntp] = r * 128;
        b_sel2[ntp] = r & 7;
    }

    float c[8][4][4];
#pragma unroll
    for (int mt = 0; mt < 8; mt++)
#pragma unroll
        for (int nt = 0; nt < 4; nt++)
#pragma unroll
            for (int i = 0; i < 4; i++) c[mt][nt][i] = 0.f;

    load_stage(0, 0);
    load_stage(1, BK);
    load_stage(2, 2 * BK);

    for (int chk = 0; chk < KCH; chk++) {
        const int rem = KCH - 1 - chk;
        if (rem >= 2)      asm volatile("cp.async.wait_group 2;" ::: "memory");
        else if (rem == 1) asm volatile("cp.async.wait_group 1;" ::: "memory");
        else               asm volatile("cp.async.wait_group 0;" ::: "memory");
        __syncthreads();

        const uint32_t base = sb + (chk % NSTG) * STG_B;
#pragma unroll
        for (int ks = 0; ks < 4; ks++) {
            uint32_t bf[2][4];
            const int ca = ks * 2 + a_hk;
            const int cb = ks * 2 + b_ch;
#pragma unroll
            for (int ntp = 0; ntp < 2; ntp++)
                ldsm_x4(bf[ntp], base + A_TILE_B + b_off[ntp] + (uint32_t)(((cb ^ b_sel2[ntp])) << 4));
#pragma unroll
            for (int mt = 0; mt < 8; mt++) {
                uint32_t ah[4];
                ldsm_x4(ah, base + a_off[mt] + (uint32_t)(((ca ^ a_sel[mt])) << 4));
#pragma unroll
                for (int nt = 0; nt < 4; nt++)
                    mma16816(c[mt][nt], ah, &bf[nt >> 1][(nt & 1) * 2]);
            }
        }

        if (chk + 3 < KCH) load_stage((chk + 3) % NSTG, (chk + 3) * BK);
    }

    const int t4 = lane >> 2;
    const int t2 = (lane & 3) * 2;
#pragma unroll
    for (int mt = 0; mt < 8; mt++) {
        const int r0 = by * BM + wr * 128 + mt * 16 + t4;
        const int r1 = r0 + 8;
#pragma unroll
        for (int nt = 0; nt < 4; nt++) {
            const int col = bx * BN + wc * 32 + nt * 8 + t2;
            const float bi0 = bias[col], bi1 = bias[col + 1];
            float2 v0 = {c[mt][nt][0] + bi0, c[mt][nt][1] + bi1};
            float2 v1 = {c[mt][nt][2] + bi0, c[mt][nt][3] + bi1};
            *(float2*)(out + (size_t)r0 * CC + col) = v0;
            *(float2*)(out + (size_t)r1 * CC + col) = v1;
        }
    }
}

// ---------------------------------------------------------------------------
// Tensor-core flash attention, fp16, exp2 domain.
// Grid: (T/64, B*H). 128 threads = 4 warps x 16 query rows (64-query tile).
// 2 CTAs/SM for cross-CTA latency hiding.
// Q split (2-pass QK), K single, P single (1-pass PV), V single.
// KV tiles of 64, double-buffered cp.async. Output: single fp16 (b,t,c).
// Smem: Qh[0:16K], Ql[16K:32K], stage s at 32K + 32K*s: {K:0, V:16K}.
// ---------------------------------------------------------------------------
static constexpr unsigned ATT_SMEM = 98304;   // 96 KB

__global__ __launch_bounds__(128, 2)
void attn_tc_kernel(const __half* __restrict__ qh, const __half* __restrict__ ql,
                    const __half* __restrict__ kh, const __half* __restrict__ vh,
                    const float* __restrict__ mask,
                    __half* __restrict__ outp)
{
    extern __shared__ char smem[];
    const uint32_t sb = smem_u32(smem);
    const int tid = threadIdx.x, lane = tid & 31, warp = tid >> 5;
    const int qb = gridDim.x - 1 - blockIdx.x;     // long CTAs first
    const int bh = blockIdx.y;
    const int b = bh >> 4, h = bh & 15;
    const int q0 = qb * 64;
    const int jmax = qb + 1;
    const size_t bhoff = (size_t)bh * TT * HD;

    // ---- Q tile load (hi + lo): 64 rows x 256B each ----
    {
        const __half* s0 = qh + bhoff + (size_t)q0 * HD;
        const __half* s1 = ql + bhoff + (size_t)q0 * HD;
#pragma unroll
        for (int i = 0; i < 8; i++) {
            const int idx = tid + i * 128;          // 1024 chunks per matrix
            const int r = idx >> 4, ch = idx & 15;
            const uint32_t off = r * 256 + ((ch ^ (r & 7)) << 4);
            cp16(sb + off,         s0 + (size_t)r * HD + ch * 8);
            cp16(sb + 16384 + off, s1 + (size_t)r * HD + ch * 8);
        }
        asm volatile("cp.async.commit_group;" ::: "memory");
    }

    auto loadKV = [&](int j, int st) {
        const uint32_t base = sb + 32768 + st * 32768;
        const int kv0 = j * 64;
        const __half* srcs[2] = {
            kh + bhoff + (size_t)kv0 * HD, vh + bhoff + (size_t)kv0 * HD };
#pragma unroll
        for (int i = 0; i < 16; i++) {
            const int idx = tid + i * 128;          // 2048 chunks
            const int mat = idx >> 10, r = (idx >> 4) & 63, ch = idx & 15;
            cp16(base + mat * 16384 + r * 256 + ((ch ^ (r & 7)) << 4),
                 srcs[mat] + (size_t)r * HD + ch * 8);
        }
        asm volatile("cp.async.commit_group;" ::: "memory");
    };

    // tile 1 prefetch is safe even when jmax==1 (rows 64..127 < T)
    loadKV(0, 0);
    loadKV(1, 1);

    float o[16][4];
#pragma unroll
    for (int n = 0; n < 16; n++)
#pragma unroll
        for (int i = 0; i < 4; i++) o[n][i] = 0.f;
    float m0 = -1e30f, m1 = -1e30f, l0 = 0.f, l1 = 0.f;

    const int qrow  = warp * 16 + (lane & 15);
    const uint32_t a_base = qrow * 256;
    const int a_sel = qrow & 7;
    const int a_kh  = lane >> 4;
    const int kb_rloc = ((lane >> 4) << 3) + (lane & 7);
    const int kb_ch   = (lane >> 3) & 1;
    const int v_rloc  = lane & 15;
    const int v_chh   = lane >> 4;

    const int qg0 = q0 + warp * 16 + (lane >> 2);
    const int qg1 = qg0 + 8;

    for (int j = 0; j < jmax; j++) {
        const int kv0 = j * 64;
        const int st = j & 1;
        if (j + 1 < jmax) asm volatile("cp.async.wait_group 1;" ::: "memory");
        else              asm volatile("cp.async.wait_group 0;" ::: "memory");
        __syncthreads();

        const uint32_t KB = sb + 32768 + st * 32768;
        const uint32_t VB = KB + 16384;

        // ---- S = Q K^T (2 split passes, Q exact), 16x64 per warp ----
        float s[8][4];
#pragma unroll
        for (int n = 0; n < 8; n++)
#pragma unroll
            for (int i = 0; i < 4; i++) s[n][i] = 0.f;

#pragma unroll
        for (int ks = 0; ks < 8; ks++) {
            uint32_t qfh[4], qfl[4];
            const uint32_t ca = (uint32_t)(((2 * ks + a_kh) ^ a_sel) << 4);
            ldsm_x4(qfh, sb + a_base + ca);
            ldsm_x4(qfl, sb + 16384 + a_base + ca);
            uint32_t kf[16];
#pragma unroll
            for (int i = 0; i < 4; i++) {
                const int r = 16 * i + kb_rloc;
                const uint32_t off = r * 256 + (((2 * ks + kb_ch) ^ (r & 7)) << 4);
                ldsm_x4(&kf[4 * i], KB + off);
            }
#pragma unroll
            for (int n = 0; n < 8; n++) {
                mma16816(s[n], qfh, &kf[2 * n]);
                mma16816(s[n], qfl, &kf[2 * n]);
            }
        }

        // ---- mask + causal (diagonal tile only) ----
        const bool need_mask = (j == qb);
#pragma unroll
        for (int n = 0; n < 8; n++) {
            const int kg = kv0 + 8 * n + 2 * (lane & 3);
            const float2 mv = *(const float2*)&mask[b * TT + kg];
            const float am0 = mv.x * LOG2E, am1 = mv.y * LOG2E;
            s[n][0] += am0; s[n][1] += am1;
            s[n][2] += am0; s[n][3] += am1;
            if (need_mask) {
                if (kg     > qg0) s[n][0] = -1e30f;
                if (kg + 1 > qg0) s[n][1] = -1e30f;
                if (kg     > qg1) s[n][2] = -1e30f;
                if (kg + 1 > qg1) s[n][3] = -1e30f;
            }
        }

        // ---- online softmax (quad-local) ----
        float mx0 = m0, mx1 = m1;
#pragma unroll
        for (int n = 0; n < 8; n++) {
            mx0 = fmaxf(mx0, fmaxf(s[n][0], s[n][1]));
            mx1 = fmaxf(mx1, fmaxf(s[n][2], s[n][3]));
        }
        mx0 = fmaxf(mx0, __shfl_xor_sync(0xffffffffu, mx0, 1));
        mx0 = fmaxf(mx0, __shfl_xor_sync(0xffffffffu, mx0, 2));
        mx1 = fmaxf(mx1, __shfl_xor_sync(0xffffffffu, mx1, 1));
        mx1 = fmaxf(mx1, __shfl_xor_sync(0xffffffffu, mx1, 2));
        const float al0 = exp2f(m0 - mx0);
        const float al1 = exp2f(m1 - mx1);
        m0 = mx0; m1 = mx1;
        float sum0 = 0.f, sum1 = 0.f;
#pragma unroll
        for (int n = 0; n < 8; n++) {
            s[n][0] = exp2f(s[n][0] - m0);
            s[n][1] = exp2f(s[n][1] - m0);
            s[n][2] = exp2f(s[n][2] - m1);
            s[n][3] = exp2f(s[n][3] - m1);
            sum0 += s[n][0] + s[n][1];
            sum1 += s[n][2] + s[n][3];
        }
        sum0 += __shfl_xor_sync(0xffffffffu, sum0, 1);
        sum0 += __shfl_xor_sync(0xffffffffu, sum0, 2);
        sum1 += __shfl_xor_sync(0xffffffffu, sum1, 1);
        sum1 += __shfl_xor_sync(0xffffffffu, sum1, 2);
        l0 = l0 * al0 + sum0;
        l1 = l1 * al1 + sum1;
#pragma unroll
        for (int n = 0; n < 16; n++) {
            o[n][0] *= al0; o[n][1] *= al0;
            o[n][2] *= al1; o[n][3] *= al1;
        }

        // ---- O += P V (register repack, P single, 1 pass) ----
#pragma unroll
        for (int kv = 0; kv < 4; kv++) {
            uint32_t pa[4];
            pa[0] = pack_h2(s[2 * kv][0],     s[2 * kv][1]);
            pa[1] = pack_h2(s[2 * kv][2],     s[2 * kv][3]);
            pa[2] = pack_h2(s[2 * kv + 1][0], s[2 * kv + 1][1]);
            pa[3] = pack_h2(s[2 * kv + 1][2], s[2 * kv + 1][3]);
            const int vr = 16 * kv + v_rloc;
            const uint32_t vro = vr * 256;
            const int vsel = vr & 7;
#pragma unroll
            for (int i = 0; i < 8; i++) {
                const uint32_t ch = (uint32_t)(((2 * i + v_chh) ^ vsel) << 4);
                uint32_t vf[4];
                ldsm_x4t(vf, VB + vro + ch);
                mma16816(o[2 * i],     pa, &vf[0]);
                mma16816(o[2 * i + 1], pa, &vf[2]);
            }
        }

        __syncthreads();
        if (j + 2 < jmax) loadKV(j + 2, st);
    }

    // ---- epilogue: normalize, single fp16, write (b,t,c) ----
    const float inv0 = 1.f / l0, inv1 = 1.f / l1;
    const size_t r0base = ((size_t)b * TT + qg0) * CC + h * HD;
    const size_t r1base = ((size_t)b * TT + qg1) * CC + h * HD;
#pragma unroll
    for (int n = 0; n < 16; n++) {
        const int d = 8 * n + 2 * (lane & 3);
        *(uint32_t*)&outp[r0base + d] = pack_h2(o[n][0] * inv0, o[n][1] * inv0);
        *(uint32_t*)&outp[r1base + d] = pack_h2(o[n][2] * inv1, o[n][3] * inv1);
    }
}

// ---------------------------------------------------------------------------
// Launcher
// ---------------------------------------------------------------------------
extern "C" void kernel_launch(void* const* d_in, const int* in_sizes, int n_in,
                              void* d_out, int out_size)
{
    const float* x    = (const float*)d_in[0];
    const float* mask = (const float*)d_in[1];
    const float* bq   = (const float*)d_in[3];
    const float* bk   = (const float*)d_in[5];
    const float* bv   = (const float*)d_in[7];
    const float* bp   = (const float*)d_in[9];
    float* out = (float*)d_out;

    __half *xp, *at, *w, *qh, *ql, *kh, *vhp;
    cudaGetSymbolAddress((void**)&xp,  g_x);
    cudaGetSymbolAddress((void**)&at,  g_at);
    cudaGetSymbolAddress((void**)&w,   g_w);
    cudaGetSymbolAddress((void**)&qh,  g_qh);
    cudaGetSymbolAddress((void**)&ql,  g_ql);
    cudaGetSymbolAddress((void**)&kh,  g_kh);
    cudaGetSymbolAddress((void**)&vhp, g_vh);

    cudaFuncSetAttribute(gemm_qkv_kernel,
                         cudaFuncAttributeMaxDynamicSharedMemorySize, GEMM_SMEM);
    cudaFuncSetAttribute(gemm1_tc_kernel,
                         cudaFuncAttributeMaxDynamicSharedMemorySize, GEMM_SMEM);
    cudaFuncSetAttribute(attn_tc_kernel,
                         cudaFuncAttributeMaxDynamicSharedMemorySize, ATT_SMEM);

    // 1. convert x and weights to fp16
    {
        const int n4x = (BB * TT * CC) / 4;
        conv_kernel<<<(n4x / 2 + 255) / 256, 256>>>(x, xp, n4x);
        const int n4w = CC * CC;          // total float4s over 4 matrices
        conv4_kernel<<<(n4w / 2 + 255) / 256, 256>>>(
            (const float*)d_in[2], (const float*)d_in[4],
            (const float*)d_in[6], (const float*)d_in[8], w);
    }

    // 2. fused QKV projection (1-pass; Q split + pre-scaled; K,V single fp16)
    gemm_qkv_kernel<<<dim3(48, MROWS / BM), 256, GEMM_SMEM>>>(
        xp, w, bq, bk, bv, qh, ql, kh, vhp);

    // 3. flash attention -> single fp16 (b,t,c); 64-query CTAs, 2 CTAs/SM
    attn_tc_kernel<<<dim3(TT / 64, BB * NH), 128, ATT_SMEM>>>(
        qh, ql, kh, vhp, mask, at);

    // 4. output projection (1-pass) -> fp32 out
    gemm1_tc_kernel<<<dim3(CC / BN, MROWS / BM), 256, GEMM_SMEM>>>(
        at, w + 3 * (size_t)CC * CC, bp, out);
}